// round 13
// baseline (speedup 1.0000x reference)
#include <cuda_runtime.h>
#include <cuda_fp16.h>
#include <cstdint>

// ---------------- problem constants ----------------
#define S_LEN  2048
#define HIDDEN 2048
#define NHEADS 16
#define HD     128
#define LATENT 512
#define BATCH  2
#define ROWS   (BATCH * S_LEN)           // 4096
#define QK_SCALE 0.12751745f             // 128^-0.5 * log2(e)
#define QKV_N  (HIDDEN + 2 * LATENT)     // 3072

// ---------------- scratch ----------------
static __device__ __half g_h16  [(size_t)ROWS * HIDDEN];
static __device__ __half g_WqkvT[(size_t)QKV_N * HIDDEN];
static __device__ __half g_WkT  [(size_t)HIDDEN * LATENT];
static __device__ __half g_WvT  [(size_t)HIDDEN * LATENT];
static __device__ __half g_WoT  [(size_t)HIDDEN * HIDDEN];
static __device__ __half g_qkv16[(size_t)ROWS * QKV_N];
static __device__ __half g_k16  [(size_t)ROWS * HIDDEN];
static __device__ __half g_vt16 [(size_t)HIDDEN * ROWS];
static __device__ __half g_ao16 [(size_t)ROWS * HIDDEN];

// ---------------- asm helpers ----------------
__device__ __forceinline__ void mma_h(float* c, const uint32_t* a,
                                      uint32_t b0, uint32_t b1) {
    asm volatile(
        "mma.sync.aligned.m16n8k16.row.col.f32.f16.f16.f32 "
        "{%0,%1,%2,%3}, {%4,%5,%6,%7}, {%8,%9}, {%0,%1,%2,%3};"
        : "+f"(c[0]), "+f"(c[1]), "+f"(c[2]), "+f"(c[3])
        : "r"(a[0]), "r"(a[1]), "r"(a[2]), "r"(a[3]), "r"(b0), "r"(b1));
}
__device__ __forceinline__ void ldsm_x4(uint32_t& r0, uint32_t& r1,
                                        uint32_t& r2, uint32_t& r3,
                                        uint32_t addr) {
    asm volatile("ldmatrix.sync.aligned.m8n8.x4.shared.b16 {%0,%1,%2,%3}, [%4];"
                 : "=r"(r0), "=r"(r1), "=r"(r2), "=r"(r3) : "r"(addr));
}
__device__ __forceinline__ void cp16(uint32_t dst, const void* src) {
    asm volatile("cp.async.cg.shared.global [%0], [%1], 16;" :: "r"(dst), "l"(src));
}
__device__ __forceinline__ void cp_commit() {
    asm volatile("cp.async.commit_group;");
}
__device__ __forceinline__ void cp_wait1() {
    asm volatile("cp.async.wait_group 1;");
}
__device__ __forceinline__ void cp_wait2() {
    asm volatile("cp.async.wait_group 2;");
}
__device__ __forceinline__ uint32_t h2pack(float hi, float lo) {
    uint32_t r;
    asm("cvt.rn.f16x2.f32 %0, %1, %2;" : "=r"(r) : "f"(hi), "f"(lo));
    return r;
}

// ---------------- pre-pass: ONE launch (h cvt + all weight transposes) ----
__global__ void prepass_all(const float* __restrict__ hsrc,
                            const float* __restrict__ Wq,
                            const float* __restrict__ Wq_rope,
                            const float* __restrict__ Wkv,
                            const float* __restrict__ Wk_up,
                            const float* __restrict__ Wk_rope,
                            const float* __restrict__ Wv_up,
                            const float* __restrict__ Wo,
                            __half* __restrict__ ph16,
                            __half* __restrict__ pWT,
                            __half* __restrict__ pWkT,
                            __half* __restrict__ pWvT,
                            __half* __restrict__ pWoT)
{
    int bid = blockIdx.x;
    int tid = threadIdx.y * 32 + threadIdx.x;

    if (bid >= 12288) {                 // h -> fp16 segment
        int idx = (bid - 12288) * 1024 + tid * 4;
        float4 v = *(const float4*)(hsrc + idx);
        __half2* p = (__half2*)(ph16 + idx);
        p[0] = __floats2half2_rn(v.x, v.y);
        p[1] = __floats2half2_rn(v.z, v.w);
        return;
    }

    __shared__ float t[32][33];
    const float *a, *a2 = nullptr;
    __half* o;
    int K, N, nbx;
    float scale = 1.f;
    if (bid < 4096)      { a = Wq;    a2 = Wq_rope; o = pWT;  K = 2048; N = 2048; nbx = 64; scale = QK_SCALE; }
    else if (bid < 6144) { bid -= 4096; a = Wkv;    o = pWT + (size_t)HIDDEN * HIDDEN; K = 2048; N = 1024; nbx = 32; }
    else if (bid < 7168) { bid -= 6144; a = Wk_up;  a2 = Wk_rope; o = pWkT; K = 512; N = 2048; nbx = 64; }
    else if (bid < 8192) { bid -= 7168; a = Wv_up;  o = pWvT; K = 512;  N = 2048; nbx = 64; }
    else                 { bid -= 8192; a = Wo;     o = pWoT; K = 2048; N = 2048; nbx = 64; }
    int n0 = (bid % nbx) * 32, k0 = (bid / nbx) * 32;
    int x = threadIdx.x, y = threadIdx.y;
#pragma unroll
    for (int i = 0; i < 4; i++) {
        int k = k0 + y + 8 * i;
        float v = a[(size_t)k * N + n0 + x];
        if (a2) v += a2[(size_t)k * N + n0 + x];
        t[y + 8 * i][x] = v;
    }
    __syncthreads();
#pragma unroll
    for (int i = 0; i < 4; i++) {
        int n = n0 + y + 8 * i;
        o[(size_t)n * K + k0 + x] = __float2half_rn(t[x][y + 8 * i] * scale);
    }
}

// =======================================================================
// fp16 mma.sync GEMM body: 128x128 CTA tile, BK=64 (halved barrier count),
// 3-stage cp.async, 2 CTAs/SM. Warp tile 32x64.
// mode 0: C fp32 [M][N]; mode 1: C fp16 [M][N]; mode 2: C fp16 [N][M].
// =======================================================================
#define GBM 128
#define GBN 128
#define GBK 64
#define ALD 72
#define BLD 72
#define STG_A (GBM * ALD)
#define STG_B (GBN * BLD)
#define STG_SZ (STG_A + STG_B)
#define G_NSTG 3
#define G_SMEM_BYTES (G_NSTG * STG_SZ * 2)    // 110592

__device__ __forceinline__
void gemm_body(int K,
               const __half* __restrict__ A, int lda,
               const __half* __restrict__ Bt, int ldb,
               void* __restrict__ C, int ldc,
               float scale, int mode,
               int bm, int bn, __half* gsm)
{
    const int tid = threadIdx.x, lane = tid & 31, wid = tid >> 5;
    const int gid = lane >> 2, t4 = lane & 3;
    const int wm = wid >> 1, wn = wid & 1;          // 4 x 2 warp grid
    const uint32_t sbase = (uint32_t)__cvta_generic_to_shared(gsm);

    // loader: 128 rows x 64 halves -> 1024 16B chunks, 4 per thread
    const int lr = tid >> 1;                        // 0..127
    const int lc = (tid & 1) * 32;                  // 0 or 32 (half index)

    auto load_stage = [&](int kt, int stg) {
        const __half* Ag = A + (size_t)bm * lda + kt * GBK;
        uint32_t as = sbase + stg * STG_SZ * 2;
#pragma unroll
        for (int i = 0; i < 4; i++)
            cp16(as + (lr * ALD + lc + i * 8) * 2, Ag + (size_t)lr * lda + lc + i * 8);
        const __half* Bg = Bt + (size_t)bn * ldb + kt * GBK;
        uint32_t bs = sbase + (stg * STG_SZ + STG_A) * 2;
#pragma unroll
        for (int i = 0; i < 4; i++)
            cp16(bs + (lr * BLD + lc + i * 8) * 2, Bg + (size_t)lr * ldb + lc + i * 8);
        cp_commit();
    };

    float acc[2][8][4];
#pragma unroll
    for (int mi = 0; mi < 2; mi++)
#pragma unroll
        for (int ni = 0; ni < 8; ni++)
#pragma unroll
            for (int x = 0; x < 4; x++) acc[mi][ni][x] = 0.f;

    const int nk = K / GBK;
    load_stage(0, 0);
    load_stage(1, 1);

    const int arow = (lane & 7) + 8 * ((lane >> 3) & 1);
    const int acol = 8 * (lane >> 4);
    const int brow = lane & 7;
    const int bcol = 8 * (lane >> 3);

    for (int kt = 0; kt < nk; kt++) {
        cp_wait1();
        __syncthreads();
        if (kt + 2 < nk) load_stage(kt + 2, (kt + 2) % G_NSTG);
        else cp_commit();

        const int stg = kt % G_NSTG;
        const uint32_t as = sbase + stg * STG_SZ * 2;
        const uint32_t bs = sbase + (stg * STG_SZ + STG_A) * 2;

#pragma unroll
        for (int kc = 0; kc < 2; kc++) {            // two 32-k halves
            uint32_t bf[8][4];
#pragma unroll
            for (int ni = 0; ni < 8; ni++) {
                int n0 = wn * 64 + ni * 8;
                ldsm_x4(bf[ni][0], bf[ni][1], bf[ni][2], bf[ni][3],
                        bs + ((n0 + brow) * BLD + kc * 32 + bcol) * 2);
            }
#pragma unroll
            for (int ks = 0; ks < 2; ks++) {
                uint32_t af[2][4];
#pragma unroll
                for (int mi = 0; mi < 2; mi++) {
                    int m0 = wm * 32 + mi * 16;
                    ldsm_x4(af[mi][0], af[mi][1], af[mi][2], af[mi][3],
                            as + ((m0 + arow) * ALD + kc * 32 + ks * 16 + acol) * 2);
                }
#pragma unroll
                for (int ni = 0; ni < 8; ni++)
#pragma unroll
                    for (int mi = 0; mi < 2; mi++)
                        mma_h(acc[mi][ni], af[mi], bf[ni][ks * 2], bf[ni][ks * 2 + 1]);
            }
        }
    }

#pragma unroll
    for (int mi = 0; mi < 2; mi++) {
        int row = bm + wm * 32 + mi * 16 + gid;
#pragma unroll
        for (int ni = 0; ni < 8; ni++) {
            int col = bn + wn * 64 + ni * 8 + 2 * t4;
            float v0 = acc[mi][ni][0] * scale;
            float v1 = acc[mi][ni][1] * scale;
            float v2 = acc[mi][ni][2] * scale;
            float v3 = acc[mi][ni][3] * scale;
            if (mode == 0) {
                float* Cf = (float*)C;
                *(float2*)(Cf + (size_t)row * ldc + col)       = make_float2(v0, v1);
                *(float2*)(Cf + (size_t)(row + 8) * ldc + col) = make_float2(v2, v3);
            } else if (mode == 1) {
                __half* Ch = (__half*)C;
                *(__half2*)(Ch + (size_t)row * ldc + col)       = __floats2half2_rn(v0, v1);
                *(__half2*)(Ch + (size_t)(row + 8) * ldc + col) = __floats2half2_rn(v2, v3);
            } else {
                __half* Ch = (__half*)C;      // [N][M], ldc = M
                Ch[(size_t)col * ldc + row]           = __float2half_rn(v0);
                Ch[(size_t)(col + 1) * ldc + row]     = __float2half_rn(v1);
                Ch[(size_t)col * ldc + row + 8]       = __float2half_rn(v2);
                Ch[(size_t)(col + 1) * ldc + row + 8] = __float2half_rn(v3);
            }
        }
    }
}

__global__ __launch_bounds__(256, 2)
void gemm_h(int M, int N, int K,
            const __half* __restrict__ A, int lda,
            const __half* __restrict__ Bt, int ldb,
            void* __restrict__ C, int ldc,
            float scale, int mode)
{
    extern __shared__ __half gsm[];
    gemm_body(K, A, lda, Bt, ldb, C, ldc, scale, mode,
              blockIdx.y * GBM, blockIdx.x * GBN, gsm);
}

__global__ __launch_bounds__(256, 2)
void gemm_kv(const __half* __restrict__ qkv,
             const __half* __restrict__ WkT,
             const __half* __restrict__ WvT,
             __half* __restrict__ Ck,
             __half* __restrict__ Cvt)
{
    extern __shared__ __half gsm[];
    if (blockIdx.z == 0) {
        gemm_body(LATENT, qkv + HIDDEN, QKV_N, WkT, LATENT, Ck, HIDDEN,
                  1.f, 1, blockIdx.y * GBM, blockIdx.x * GBN, gsm);
    } else {
        gemm_body(LATENT, qkv + HIDDEN + LATENT, QKV_N, WvT, LATENT, Cvt, ROWS,
                  1.f, 2, blockIdx.y * GBM, blockIdx.x * GBN, gsm);
    }
}

// =======================================================================
// fp16 flash attention — round-11 version (best measured: 144us).
// 128 thr, Br=64, Bc=64, 2 CTAs/SM, 2-stage ring, Q frags persistent.
// =======================================================================
#define QLDH 136
#define KLDH 136
#define VLDH 72
#define Q_SZ   (64 * QLDH)
#define K_STG  (64 * KLDH)
#define V_STG  (128 * VLDH)
#define K_OFF  Q_SZ
#define V_OFF  (Q_SZ + 2 * K_STG)
#define FA_SMEM_BYTES ((Q_SZ + 2 * (K_STG + V_STG)) * 2)   // 89088

__global__ __launch_bounds__(128)
void flash_attn_h(const __half* __restrict__ Qg,      // packed qkv, ld = 3072
                  const __half* __restrict__ Kg,
                  const __half* __restrict__ Vtg,     // [2048][4096]
                  __half* __restrict__ Og)
{
    extern __shared__ __half fsm[];
    const uint32_t sb = (uint32_t)__cvta_generic_to_shared(fsm);

    const int qt   = (gridDim.x - 1) - blockIdx.x;
    const int bh   = blockIdx.y;
    const int b    = bh >> 4;
    const int h    = bh & 15;
    const int tid  = threadIdx.x;
    const int lane = tid & 31;
    const int wid  = tid >> 5;
    const int gid  = lane >> 2;
    const int t4   = lane & 3;

    {
        const __half* qb = Qg + (size_t)(b * S_LEN + qt * 64) * QKV_N + h * HD;
#pragma unroll
        for (int i = 0; i < 8; i++) {
            int g = tid + 128 * i;
            int r = g >> 4, c = (g & 15) * 8;
            cp16(sb + (r * QLDH + c) * 2, qb + (size_t)r * QKV_N + c);
        }
        cp_commit();
    }

    auto load_kv = [&](int kt, int stg) {
        const __half* kb = Kg + (size_t)(b * S_LEN + kt * 64) * HIDDEN + h * HD;
        uint32_t ks = sb + (K_OFF + stg * K_STG) * 2;
#pragma unroll
        for (int i = 0; i < 8; i++) {
            int g = tid + 128 * i;
            int r = g >> 4, c = (g & 15) * 8;
            cp16(ks + (r * KLDH + c) * 2, kb + (size_t)r * HIDDEN + c);
        }
        const __half* vb = Vtg + (size_t)(h * HD) * ROWS + b * S_LEN + kt * 64;
        uint32_t vs = sb + (V_OFF + stg * V_STG) * 2;
#pragma unroll
        for (int i = 0; i < 8; i++) {
            int g = tid + 128 * i;
            int r = g >> 3, c = (g & 7) * 8;
            cp16(vs + (r * VLDH + c) * 2, vb + (size_t)r * ROWS + c);
        }
        cp_commit();
    };

    const int nkt = qt + 1;
    load_kv(0, 0);

    const int arow = (lane & 7) + 8 * ((lane >> 3) & 1);
    const int acol = 8 * (lane >> 4);
    const int brow = lane & 7;
    const int bcol = 8 * (lane >> 3);
    const int r0 = wid * 16;

    uint32_t q[8][4];
    cp_wait1();
    __syncthreads();
#pragma unroll
    for (int ks = 0; ks < 8; ks++)
        ldsm_x4(q[ks][0], q[ks][1], q[ks][2], q[ks][3],
                sb + ((r0 + arow) * QLDH + ks * 16 + acol) * 2);

    float o[16][4];
#pragma unroll
    for (int ni = 0; ni < 16; ni++)
#pragma unroll
        for (int x = 0; x < 4; x++) o[ni][x] = 0.f;
    float m_lo = -1e30f, m_hi = -1e30f, l_lo = 0.f, l_hi = 0.f;

    const int row_lo = qt * 64 + r0 + gid;
    const int row_hi = row_lo + 8;

    for (int kt = 0; kt < nkt; kt++) {
        const int stg = kt & 1;
        __syncthreads();
        if (kt + 1 < nkt) load_kv(kt + 1, stg ^ 1);
        else cp_commit();
        cp_wait1();
        __syncthreads();

        const uint32_t ksb = sb + (K_OFF + stg * K_STG) * 2;
        const uint32_t vsb = sb + (V_OFF + stg * V_STG) * 2;

        float s[8][4];
#pragma unroll
        for (int ni = 0; ni < 8; ni++)
#pragma unroll
            for (int x = 0; x < 4; x++) s[ni][x] = 0.f;

#pragma unroll
        for (int kc = 0; kc < 4; kc++) {
#pragma unroll
            for (int ni = 0; ni < 8; ni++) {
                uint32_t kb4[4];
                ldsm_x4(kb4[0], kb4[1], kb4[2], kb4[3],
                        ksb + ((ni * 8 + brow) * KLDH + kc * 32 + bcol) * 2);
                mma_h(s[ni], q[kc * 2],     kb4[0], kb4[1]);
                mma_h(s[ni], q[kc * 2 + 1], kb4[2], kb4[3]);
            }
        }

        if (kt == qt) {
            const int cb = kt * 64 + 2 * t4;
#pragma unroll
            for (int ni = 0; ni < 8; ni++) {
                int c0 = cb + ni * 8;
                if (c0     > row_lo) s[ni][0] = -1e30f;
                if (c0 + 1 > row_lo) s[ni][1] = -1e30f;
                if (c0     > row_hi) s[ni][2] = -1e30f;
                if (c0 + 1 > row_hi) s[ni][3] = -1e30f;
            }
        }

        float mlo = -1e30f, mhi = -1e30f;
#pragma unroll
        for (int ni = 0; ni < 8; ni++) {
            mlo = fmaxf(mlo, fmaxf(s[ni][0], s[ni][1]));
            mhi = fmaxf(mhi, fmaxf(s[ni][2], s[ni][3]));
        }
        mlo = fmaxf(mlo, __shfl_xor_sync(0xffffffffu, mlo, 1));
        mlo = fmaxf(mlo, __shfl_xor_sync(0xffffffffu, mlo, 2));
        mhi = fmaxf(mhi, __shfl_xor_sync(0xffffffffu, mhi, 1));
        mhi = fmaxf(mhi, __shfl_xor_sync(0xffffffffu, mhi, 2));

        float mnl = fmaxf(m_lo, mlo), mnh = fmaxf(m_hi, mhi);
        float clo = exp2f(m_lo - mnl), chi = exp2f(m_hi - mnh);
        m_lo = mnl; m_hi = mnh;

        float rlo = 0.f, rhi = 0.f;
#pragma unroll
        for (int ni = 0; ni < 8; ni++) {
            s[ni][0] = exp2f(s[ni][0] - mnl);
            s[ni][1] = exp2f(s[ni][1] - mnl);
            s[ni][2] = exp2f(s[ni][2] - mnh);
            s[ni][3] = exp2f(s[ni][3] - mnh);
            rlo += s[ni][0] + s[ni][1];
            rhi += s[ni][2] + s[ni][3];
        }
        rlo += __shfl_xor_sync(0xffffffffu, rlo, 1);
        rlo += __shfl_xor_sync(0xffffffffu, rlo, 2);
        rhi += __shfl_xor_sync(0xffffffffu, rhi, 1);
        rhi += __shfl_xor_sync(0xffffffffu, rhi, 2);
        l_lo = l_lo * clo + rlo;
        l_hi = l_hi * chi + rhi;

#pragma unroll
        for (int ni = 0; ni < 16; ni++) {
            o[ni][0] *= clo; o[ni][1] *= clo;
            o[ni][2] *= chi; o[ni][3] *= chi;
        }

        uint32_t pa[4][4];
#pragma unroll
        for (int kc = 0; kc < 4; kc++) {
            pa[kc][0] = h2pack(s[2 * kc][1],     s[2 * kc][0]);
            pa[kc][1] = h2pack(s[2 * kc][3],     s[2 * kc][2]);
            pa[kc][2] = h2pack(s[2 * kc + 1][1], s[2 * kc + 1][0]);
            pa[kc][3] = h2pack(s[2 * kc + 1][3], s[2 * kc + 1][2]);
        }

#pragma unroll
        for (int vc = 0; vc < 2; vc++) {
#pragma unroll
            for (int ni = 0; ni < 16; ni++) {
                uint32_t vb4[4];
                ldsm_x4(vb4[0], vb4[1], vb4[2], vb4[3],
                        vsb + ((ni * 8 + brow) * VLDH + vc * 32 + bcol) * 2);
                mma_h(o[ni], pa[vc * 2],     vb4[0], vb4[1]);
                mma_h(o[ni], pa[vc * 2 + 1], vb4[2], vb4[3]);
            }
        }
    }

    const float il0 = 1.f / l_lo, il1 = 1.f / l_hi;
    __half* olo = Og + (size_t)(b * S_LEN + row_lo) * HIDDEN + h * HD;
    __half* ohi = Og + (size_t)(b * S_LEN + row_hi) * HIDDEN + h * HD;
#pragma unroll
    for (int ni = 0; ni < 16; ni++) {
        int col = ni * 8 + 2 * t4;
        *(__half2*)(olo + col) = __floats2half2_rn(o[ni][0] * il0, o[ni][1] * il0);
        *(__half2*)(ohi + col) = __floats2half2_rn(o[ni][2] * il1, o[ni][3] * il1);
    }
}

// ---------------- launch ----------------
extern "C" void kernel_launch(void* const* d_in, const int* in_sizes, int n_in,
                              void* d_out, int out_size)
{
    const float* h       = (const float*)d_in[0];
    const float* Wq      = (const float*)d_in[3];
    const float* Wkv     = (const float*)d_in[4];
    const float* Wk_up   = (const float*)d_in[5];
    const float* Wv_up   = (const float*)d_in[6];
    const float* Wq_rope = (const float*)d_in[7];
    const float* Wk_rope = (const float*)d_in[8];
    const float* Wo      = (const float*)d_in[9];
    float* out = (float*)d_out;

    __half *ph16, *pWT, *pWkT, *pWvT, *pWoT, *pqkv, *pk, *pvt, *pao;
    cudaGetSymbolAddress((void**)&ph16, g_h16);
    cudaGetSymbolAddress((void**)&pWT,  g_WqkvT);
    cudaGetSymbolAddress((void**)&pWkT, g_WkT);
    cudaGetSymbolAddress((void**)&pWvT, g_WvT);
    cudaGetSymbolAddress((void**)&pWoT, g_WoT);
    cudaGetSymbolAddress((void**)&pqkv, g_qkv16);
    cudaGetSymbolAddress((void**)&pk,   g_k16);
    cudaGetSymbolAddress((void**)&pvt,  g_vt16);
    cudaGetSymbolAddress((void**)&pao,  g_ao16);

    static int attr_done = 0;
    if (!attr_done) {
        cudaFuncSetAttribute(gemm_h,
            cudaFuncAttributeMaxDynamicSharedMemorySize, G_SMEM_BYTES);
        cudaFuncSetAttribute(gemm_kv,
            cudaFuncAttributeMaxDynamicSharedMemorySize, G_SMEM_BYTES);
        cudaFuncSetAttribute(flash_attn_h,
            cudaFuncAttributeMaxDynamicSharedMemorySize, FA_SMEM_BYTES);
        attr_done = 1;
    }

    dim3 blk(256);
    // launch 0: prepass (h cvt + all weight transposes)
    prepass_all<<<20480, dim3(32, 8)>>>(h, Wq, Wq_rope, Wkv, Wk_up, Wk_rope,
                                        Wv_up, Wo, ph16, pWT, pWkT, pWvT, pWoT);

    // launch 1: qkv = fp16(h @ [Wq_eff*s | Wkv])
    gemm_h<<<dim3(QKV_N / GBN, ROWS / GBM), blk, G_SMEM_BYTES>>>(
        ROWS, QKV_N, HIDDEN, ph16, HIDDEN, pWT, HIDDEN, pqkv, QKV_N, 1.f, 1);

    // launch 2: k AND v^T in one launch (grid.z)
    gemm_kv<<<dim3(HIDDEN / GBN, ROWS / GBM, 2), blk, G_SMEM_BYTES>>>(
        pqkv, pWkT, pWvT, pk, pvt);

    // launch 3: attention — Br=64, 128 threads, 2 CTAs/SM
    flash_attn_h<<<dim3(S_LEN / 64, BATCH * NHEADS), 128, FA_SMEM_BYTES>>>(
        pqkv, pk, pvt, pao);

    // launch 4: out = fp32(ao @ Wo)
    gemm_h<<<dim3(HIDDEN / GBN, ROWS / GBM), blk, G_SMEM_BYTES>>>(
        ROWS, HIDDEN, HIDDEN, pao, HIDDEN, pWoT, HIDDEN, out, HIDDEN, 1.f, 0);
}

// round 14
// speedup vs baseline: 1.1013x; 1.1013x over previous
#include <cuda_runtime.h>
#include <cuda_fp16.h>
#include <cstdint>

// ---------------- problem constants ----------------
#define S_LEN  2048
#define HIDDEN 2048
#define NHEADS 16
#define HD     128
#define LATENT 512
#define BATCH  2
#define ROWS   (BATCH * S_LEN)           // 4096
#define QK_SCALE 0.12751745f             // 128^-0.5 * log2(e)
#define QKV_N  (HIDDEN + 2 * LATENT)     // 3072

// ---------------- scratch ----------------
static __device__ __half g_h16  [(size_t)ROWS * HIDDEN];
static __device__ __half g_WqkvT[(size_t)QKV_N * HIDDEN];
static __device__ __half g_WkT  [(size_t)HIDDEN * LATENT];
static __device__ __half g_WvT  [(size_t)HIDDEN * LATENT];
static __device__ __half g_WoT  [(size_t)HIDDEN * HIDDEN];
static __device__ __half g_qkv16[(size_t)ROWS * QKV_N];
static __device__ __half g_k16  [(size_t)ROWS * HIDDEN];
static __device__ __half g_vt16 [(size_t)HIDDEN * ROWS];
static __device__ __half g_ao16 [(size_t)ROWS * HIDDEN];

// ---------------- asm helpers ----------------
__device__ __forceinline__ void mma_h(float* c, const uint32_t* a,
                                      uint32_t b0, uint32_t b1) {
    asm volatile(
        "mma.sync.aligned.m16n8k16.row.col.f32.f16.f16.f32 "
        "{%0,%1,%2,%3}, {%4,%5,%6,%7}, {%8,%9}, {%0,%1,%2,%3};"
        : "+f"(c[0]), "+f"(c[1]), "+f"(c[2]), "+f"(c[3])
        : "r"(a[0]), "r"(a[1]), "r"(a[2]), "r"(a[3]), "r"(b0), "r"(b1));
}
__device__ __forceinline__ void ldsm_x4(uint32_t& r0, uint32_t& r1,
                                        uint32_t& r2, uint32_t& r3,
                                        uint32_t addr) {
    asm volatile("ldmatrix.sync.aligned.m8n8.x4.shared.b16 {%0,%1,%2,%3}, [%4];"
                 : "=r"(r0), "=r"(r1), "=r"(r2), "=r"(r3) : "r"(addr));
}
__device__ __forceinline__ void cp16(uint32_t dst, const void* src) {
    asm volatile("cp.async.cg.shared.global [%0], [%1], 16;" :: "r"(dst), "l"(src));
}
__device__ __forceinline__ void cp_commit() {
    asm volatile("cp.async.commit_group;");
}
__device__ __forceinline__ void cp_wait1() {
    asm volatile("cp.async.wait_group 1;");
}
__device__ __forceinline__ void cp_wait2() {
    asm volatile("cp.async.wait_group 2;");
}
__device__ __forceinline__ uint32_t h2pack(float hi, float lo) {
    uint32_t r;
    asm("cvt.rn.f16x2.f32 %0, %1, %2;" : "=r"(r) : "f"(hi), "f"(lo));
    return r;
}

// ---------------- pre-pass: ONE launch (h cvt + all weight transposes) ----
__global__ void prepass_all(const float* __restrict__ hsrc,
                            const float* __restrict__ Wq,
                            const float* __restrict__ Wq_rope,
                            const float* __restrict__ Wkv,
                            const float* __restrict__ Wk_up,
                            const float* __restrict__ Wk_rope,
                            const float* __restrict__ Wv_up,
                            const float* __restrict__ Wo,
                            __half* __restrict__ ph16,
                            __half* __restrict__ pWT,
                            __half* __restrict__ pWkT,
                            __half* __restrict__ pWvT,
                            __half* __restrict__ pWoT)
{
    int bid = blockIdx.x;
    int tid = threadIdx.y * 32 + threadIdx.x;

    if (bid >= 12288) {                 // h -> fp16 segment
        int idx = (bid - 12288) * 1024 + tid * 4;
        float4 v = *(const float4*)(hsrc + idx);
        __half2* p = (__half2*)(ph16 + idx);
        p[0] = __floats2half2_rn(v.x, v.y);
        p[1] = __floats2half2_rn(v.z, v.w);
        return;
    }

    __shared__ float t[32][33];
    const float *a, *a2 = nullptr;
    __half* o;
    int K, N, nbx;
    float scale = 1.f;
    if (bid < 4096)      { a = Wq;    a2 = Wq_rope; o = pWT;  K = 2048; N = 2048; nbx = 64; scale = QK_SCALE; }
    else if (bid < 6144) { bid -= 4096; a = Wkv;    o = pWT + (size_t)HIDDEN * HIDDEN; K = 2048; N = 1024; nbx = 32; }
    else if (bid < 7168) { bid -= 6144; a = Wk_up;  a2 = Wk_rope; o = pWkT; K = 512; N = 2048; nbx = 64; }
    else if (bid < 8192) { bid -= 7168; a = Wv_up;  o = pWvT; K = 512;  N = 2048; nbx = 64; }
    else                 { bid -= 8192; a = Wo;     o = pWoT; K = 2048; N = 2048; nbx = 64; }
    int n0 = (bid % nbx) * 32, k0 = (bid / nbx) * 32;
    int x = threadIdx.x, y = threadIdx.y;
#pragma unroll
    for (int i = 0; i < 4; i++) {
        int k = k0 + y + 8 * i;
        float v = a[(size_t)k * N + n0 + x];
        if (a2) v += a2[(size_t)k * N + n0 + x];
        t[y + 8 * i][x] = v;
    }
    __syncthreads();
#pragma unroll
    for (int i = 0; i < 4; i++) {
        int n = n0 + y + 8 * i;
        o[(size_t)n * K + k0 + x] = __float2half_rn(t[x][y + 8 * i] * scale);
    }
}

// =======================================================================
// fp16 mma.sync GEMM body (round-11 exact): 128x128, BK=32, 4-stage
// cp.async, 2 CTAs/SM, warp tile 32x64.
// =======================================================================
#define GBM 128
#define GBN 128
#define GBK 32
#define ALD 40
#define BLD 40
#define STG_A (GBM * ALD)
#define STG_B (GBN * BLD)
#define STG_SZ (STG_A + STG_B)
#define G_NSTG 4
#define G_SMEM_BYTES (G_NSTG * STG_SZ * 2)

__device__ __forceinline__
void gemm_body(int K,
               const __half* __restrict__ A, int lda,
               const __half* __restrict__ Bt, int ldb,
               void* __restrict__ C, int ldc,
               float scale, int mode,
               int bm, int bn, __half* gsm)
{
    const int tid = threadIdx.x, lane = tid & 31, wid = tid >> 5;
    const int gid = lane >> 2, t4 = lane & 3;
    const int wm = wid >> 1, wn = wid & 1;
    const uint32_t sbase = (uint32_t)__cvta_generic_to_shared(gsm);

    const int ar = tid >> 2;
    const int ac = (tid & 3) * 8;

    auto load_stage = [&](int kt, int stg) {
        const __half* Ag = A + (size_t)bm * lda + kt * GBK;
        uint32_t as = sbase + stg * STG_SZ * 2;
#pragma unroll
        for (int i = 0; i < 2; i++) {
            int r = ar + 64 * i;
            cp16(as + (r * ALD + ac) * 2, Ag + (size_t)r * lda + ac);
        }
        const __half* Bg = Bt + (size_t)bn * ldb + kt * GBK;
        uint32_t bs = sbase + (stg * STG_SZ + STG_A) * 2;
#pragma unroll
        for (int i = 0; i < 2; i++) {
            int r = ar + 64 * i;
            cp16(bs + (r * BLD + ac) * 2, Bg + (size_t)r * ldb + ac);
        }
        cp_commit();
    };

    float acc[2][8][4];
#pragma unroll
    for (int mi = 0; mi < 2; mi++)
#pragma unroll
        for (int ni = 0; ni < 8; ni++)
#pragma unroll
            for (int x = 0; x < 4; x++) acc[mi][ni][x] = 0.f;

    const int nk = K / GBK;
    load_stage(0, 0);
    load_stage(1, 1);
    load_stage(2, 2);

    const int arow = (lane & 7) + 8 * ((lane >> 3) & 1);
    const int acol = 8 * (lane >> 4);
    const int brow = lane & 7;
    const int bcol = 8 * (lane >> 3);

    for (int kt = 0; kt < nk; kt++) {
        cp_wait2();
        __syncthreads();
        if (kt + 3 < nk) load_stage(kt + 3, (kt + 3) % G_NSTG);
        else cp_commit();

        const int stg = kt % G_NSTG;
        const uint32_t as = sbase + stg * STG_SZ * 2;
        const uint32_t bs = sbase + (stg * STG_SZ + STG_A) * 2;

        uint32_t bf[8][4];
#pragma unroll
        for (int ni = 0; ni < 8; ni++) {
            int n0 = wn * 64 + ni * 8;
            ldsm_x4(bf[ni][0], bf[ni][1], bf[ni][2], bf[ni][3],
                    bs + ((n0 + brow) * BLD + bcol) * 2);
        }
#pragma unroll
        for (int ks = 0; ks < 2; ks++) {
            uint32_t af[2][4];
#pragma unroll
            for (int mi = 0; mi < 2; mi++) {
                int m0 = wm * 32 + mi * 16;
                ldsm_x4(af[mi][0], af[mi][1], af[mi][2], af[mi][3],
                        as + ((m0 + arow) * ALD + ks * 16 + acol) * 2);
            }
#pragma unroll
            for (int ni = 0; ni < 8; ni++)
#pragma unroll
                for (int mi = 0; mi < 2; mi++)
                    mma_h(acc[mi][ni], af[mi], bf[ni][ks * 2], bf[ni][ks * 2 + 1]);
        }
    }

#pragma unroll
    for (int mi = 0; mi < 2; mi++) {
        int row = bm + wm * 32 + mi * 16 + gid;
#pragma unroll
        for (int ni = 0; ni < 8; ni++) {
            int col = bn + wn * 64 + ni * 8 + 2 * t4;
            float v0 = acc[mi][ni][0] * scale;
            float v1 = acc[mi][ni][1] * scale;
            float v2 = acc[mi][ni][2] * scale;
            float v3 = acc[mi][ni][3] * scale;
            if (mode == 0) {
                float* Cf = (float*)C;
                *(float2*)(Cf + (size_t)row * ldc + col)       = make_float2(v0, v1);
                *(float2*)(Cf + (size_t)(row + 8) * ldc + col) = make_float2(v2, v3);
            } else if (mode == 1) {
                __half* Ch = (__half*)C;
                *(__half2*)(Ch + (size_t)row * ldc + col)       = __floats2half2_rn(v0, v1);
                *(__half2*)(Ch + (size_t)(row + 8) * ldc + col) = __floats2half2_rn(v2, v3);
            } else {
                __half* Ch = (__half*)C;      // [N][M], ldc = M
                Ch[(size_t)col * ldc + row]           = __float2half_rn(v0);
                Ch[(size_t)(col + 1) * ldc + row]     = __float2half_rn(v1);
                Ch[(size_t)col * ldc + row + 8]       = __float2half_rn(v2);
                Ch[(size_t)(col + 1) * ldc + row + 8] = __float2half_rn(v3);
            }
        }
    }
}

__global__ __launch_bounds__(256, 2)
void gemm_h(int M, int N, int K,
            const __half* __restrict__ A, int lda,
            const __half* __restrict__ Bt, int ldb,
            void* __restrict__ C, int ldc,
            float scale, int mode)
{
    extern __shared__ __half gsm[];
    gemm_body(K, A, lda, Bt, ldb, C, ldc, scale, mode,
              blockIdx.y * GBM, blockIdx.x * GBN, gsm);
}

__global__ __launch_bounds__(256, 2)
void gemm_kv(const __half* __restrict__ qkv,
             const __half* __restrict__ WkT,
             const __half* __restrict__ WvT,
             __half* __restrict__ Ck,
             __half* __restrict__ Cvt)
{
    extern __shared__ __half gsm[];
    if (blockIdx.z == 0) {
        gemm_body(LATENT, qkv + HIDDEN, QKV_N, WkT, LATENT, Ck, HIDDEN,
                  1.f, 1, blockIdx.y * GBM, blockIdx.x * GBN, gsm);
    } else {
        gemm_body(LATENT, qkv + HIDDEN + LATENT, QKV_N, WvT, LATENT, Cvt, ROWS,
                  1.f, 2, blockIdx.y * GBM, blockIdx.x * GBN, gsm);
    }
}

// =======================================================================
// fp16 flash attention — round-11 structure + software-pipelined LDSM
// (1-deep double-buffered fragments in S and PV phases).
// 128 thr, Br=64, Bc=64, 2 CTAs/SM, 2-stage ring, Q frags persistent.
// =======================================================================
#define QLDH 136
#define KLDH 136
#define VLDH 72
#define Q_SZ   (64 * QLDH)
#define K_STG  (64 * KLDH)
#define V_STG  (128 * VLDH)
#define K_OFF  Q_SZ
#define V_OFF  (Q_SZ + 2 * K_STG)
#define FA_SMEM_BYTES ((Q_SZ + 2 * (K_STG + V_STG)) * 2)   // 89088

__global__ __launch_bounds__(128)
void flash_attn_h(const __half* __restrict__ Qg,      // packed qkv, ld = 3072
                  const __half* __restrict__ Kg,
                  const __half* __restrict__ Vtg,     // [2048][4096]
                  __half* __restrict__ Og)
{
    extern __shared__ __half fsm[];
    const uint32_t sb = (uint32_t)__cvta_generic_to_shared(fsm);

    const int qt   = (gridDim.x - 1) - blockIdx.x;
    const int bh   = blockIdx.y;
    const int b    = bh >> 4;
    const int h    = bh & 15;
    const int tid  = threadIdx.x;
    const int lane = tid & 31;
    const int wid  = tid >> 5;
    const int gid  = lane >> 2;
    const int t4   = lane & 3;

    {
        const __half* qb = Qg + (size_t)(b * S_LEN + qt * 64) * QKV_N + h * HD;
#pragma unroll
        for (int i = 0; i < 8; i++) {
            int g = tid + 128 * i;
            int r = g >> 4, c = (g & 15) * 8;
            cp16(sb + (r * QLDH + c) * 2, qb + (size_t)r * QKV_N + c);
        }
        cp_commit();
    }

    auto load_kv = [&](int kt, int stg) {
        const __half* kb = Kg + (size_t)(b * S_LEN + kt * 64) * HIDDEN + h * HD;
        uint32_t ks = sb + (K_OFF + stg * K_STG) * 2;
#pragma unroll
        for (int i = 0; i < 8; i++) {
            int g = tid + 128 * i;
            int r = g >> 4, c = (g & 15) * 8;
            cp16(ks + (r * KLDH + c) * 2, kb + (size_t)r * HIDDEN + c);
        }
        const __half* vb = Vtg + (size_t)(h * HD) * ROWS + b * S_LEN + kt * 64;
        uint32_t vs = sb + (V_OFF + stg * V_STG) * 2;
#pragma unroll
        for (int i = 0; i < 8; i++) {
            int g = tid + 128 * i;
            int r = g >> 3, c = (g & 7) * 8;
            cp16(vs + (r * VLDH + c) * 2, vb + (size_t)r * ROWS + c);
        }
        cp_commit();
    };

    const int nkt = qt + 1;
    load_kv(0, 0);

    const int arow = (lane & 7) + 8 * ((lane >> 3) & 1);
    const int acol = 8 * (lane >> 4);
    const int brow = lane & 7;
    const int bcol = 8 * (lane >> 3);
    const int r0 = wid * 16;

    uint32_t q[8][4];
    cp_wait1();
    __syncthreads();
#pragma unroll
    for (int ks = 0; ks < 8; ks++)
        ldsm_x4(q[ks][0], q[ks][1], q[ks][2], q[ks][3],
                sb + ((r0 + arow) * QLDH + ks * 16 + acol) * 2);

    float o[16][4];
#pragma unroll
    for (int ni = 0; ni < 16; ni++)
#pragma unroll
        for (int x = 0; x < 4; x++) o[ni][x] = 0.f;
    float m_lo = -1e30f, m_hi = -1e30f, l_lo = 0.f, l_hi = 0.f;

    const int row_lo = qt * 64 + r0 + gid;
    const int row_hi = row_lo + 8;

    for (int kt = 0; kt < nkt; kt++) {
        const int stg = kt & 1;
        __syncthreads();
        if (kt + 1 < nkt) load_kv(kt + 1, stg ^ 1);
        else cp_commit();
        cp_wait1();
        __syncthreads();

        const uint32_t ksb = sb + (K_OFF + stg * K_STG) * 2;
        const uint32_t vsb = sb + (V_OFF + stg * V_STG) * 2;

        // ---- S = Q @ K^T, software-pipelined LDSM ----
        float s[8][4];
#pragma unroll
        for (int ni = 0; ni < 8; ni++)
#pragma unroll
            for (int x = 0; x < 4; x++) s[ni][x] = 0.f;

        {
            uint32_t kbuf[2][4];
            // it -> kc = it>>3, ni = it&7
            ldsm_x4(kbuf[0][0], kbuf[0][1], kbuf[0][2], kbuf[0][3],
                    ksb + (brow * KLDH + bcol) * 2);
#pragma unroll
            for (int it = 0; it < 32; it++) {
                if (it + 1 < 32) {
                    int kc_n = (it + 1) >> 3, ni_n = (it + 1) & 7;
                    ldsm_x4(kbuf[(it + 1) & 1][0], kbuf[(it + 1) & 1][1],
                            kbuf[(it + 1) & 1][2], kbuf[(it + 1) & 1][3],
                            ksb + ((ni_n * 8 + brow) * KLDH + kc_n * 32 + bcol) * 2);
                }
                const int kc = it >> 3, ni = it & 7;
                const uint32_t* kb4 = kbuf[it & 1];
                mma_h(s[ni], q[kc * 2],     kb4[0], kb4[1]);
                mma_h(s[ni], q[kc * 2 + 1], kb4[2], kb4[3]);
            }
        }

        if (kt == qt) {
            const int cb = kt * 64 + 2 * t4;
#pragma unroll
            for (int ni = 0; ni < 8; ni++) {
                int c0 = cb + ni * 8;
                if (c0     > row_lo) s[ni][0] = -1e30f;
                if (c0 + 1 > row_lo) s[ni][1] = -1e30f;
                if (c0     > row_hi) s[ni][2] = -1e30f;
                if (c0 + 1 > row_hi) s[ni][3] = -1e30f;
            }
        }

        float mlo = -1e30f, mhi = -1e30f;
#pragma unroll
        for (int ni = 0; ni < 8; ni++) {
            mlo = fmaxf(mlo, fmaxf(s[ni][0], s[ni][1]));
            mhi = fmaxf(mhi, fmaxf(s[ni][2], s[ni][3]));
        }
        mlo = fmaxf(mlo, __shfl_xor_sync(0xffffffffu, mlo, 1));
        mlo = fmaxf(mlo, __shfl_xor_sync(0xffffffffu, mlo, 2));
        mhi = fmaxf(mhi, __shfl_xor_sync(0xffffffffu, mhi, 1));
        mhi = fmaxf(mhi, __shfl_xor_sync(0xffffffffu, mhi, 2));

        float mnl = fmaxf(m_lo, mlo), mnh = fmaxf(m_hi, mhi);
        float clo = exp2f(m_lo - mnl), chi = exp2f(m_hi - mnh);
        m_lo = mnl; m_hi = mnh;

        float rlo = 0.f, rhi = 0.f;
#pragma unroll
        for (int ni = 0; ni < 8; ni++) {
            s[ni][0] = exp2f(s[ni][0] - mnl);
            s[ni][1] = exp2f(s[ni][1] - mnl);
            s[ni][2] = exp2f(s[ni][2] - mnh);
            s[ni][3] = exp2f(s[ni][3] - mnh);
            rlo += s[ni][0] + s[ni][1];
            rhi += s[ni][2] + s[ni][3];
        }
        rlo += __shfl_xor_sync(0xffffffffu, rlo, 1);
        rlo += __shfl_xor_sync(0xffffffffu, rlo, 2);
        rhi += __shfl_xor_sync(0xffffffffu, rhi, 1);
        rhi += __shfl_xor_sync(0xffffffffu, rhi, 2);
        l_lo = l_lo * clo + rlo;
        l_hi = l_hi * chi + rhi;

#pragma unroll
        for (int ni = 0; ni < 16; ni++) {
            o[ni][0] *= clo; o[ni][1] *= clo;
            o[ni][2] *= chi; o[ni][3] *= chi;
        }

        uint32_t pa[4][4];
#pragma unroll
        for (int kc = 0; kc < 4; kc++) {
            pa[kc][0] = h2pack(s[2 * kc][1],     s[2 * kc][0]);
            pa[kc][1] = h2pack(s[2 * kc][3],     s[2 * kc][2]);
            pa[kc][2] = h2pack(s[2 * kc + 1][1], s[2 * kc + 1][0]);
            pa[kc][3] = h2pack(s[2 * kc + 1][3], s[2 * kc + 1][2]);
        }

        // ---- O += P @ V, software-pipelined LDSM ----
        {
            uint32_t vbuf[2][4];
            // it -> vc = it>>4, ni = it&15
            ldsm_x4(vbuf[0][0], vbuf[0][1], vbuf[0][2], vbuf[0][3],
                    vsb + (brow * VLDH + bcol) * 2);
#pragma unroll
            for (int it = 0; it < 32; it++) {
                if (it + 1 < 32) {
                    int vc_n = (it + 1) >> 4, ni_n = (it + 1) & 15;
                    ldsm_x4(vbuf[(it + 1) & 1][0], vbuf[(it + 1) & 1][1],
                            vbuf[(it + 1) & 1][2], vbuf[(it + 1) & 1][3],
                            vsb + ((ni_n * 8 + brow) * VLDH + vc_n * 32 + bcol) * 2);
                }
                const int vc = it >> 4, ni = it & 15;
                const uint32_t* vb4 = vbuf[it & 1];
                mma_h(o[ni], pa[vc * 2],     vb4[0], vb4[1]);
                mma_h(o[ni], pa[vc * 2 + 1], vb4[2], vb4[3]);
            }
        }
    }

    const float il0 = 1.f / l_lo, il1 = 1.f / l_hi;
    __half* olo = Og + (size_t)(b * S_LEN + row_lo) * HIDDEN + h * HD;
    __half* ohi = Og + (size_t)(b * S_LEN + row_hi) * HIDDEN + h * HD;
#pragma unroll
    for (int ni = 0; ni < 16; ni++) {
        int col = ni * 8 + 2 * t4;
        *(__half2*)(olo + col) = __floats2half2_rn(o[ni][0] * il0, o[ni][1] * il0);
        *(__half2*)(ohi + col) = __floats2half2_rn(o[ni][2] * il1, o[ni][3] * il1);
    }
}

// ---------------- launch ----------------
extern "C" void kernel_launch(void* const* d_in, const int* in_sizes, int n_in,
                              void* d_out, int out_size)
{
    const float* h       = (const float*)d_in[0];
    const float* Wq      = (const float*)d_in[3];
    const float* Wkv     = (const float*)d_in[4];
    const float* Wk_up   = (const float*)d_in[5];
    const float* Wv_up   = (const float*)d_in[6];
    const float* Wq_rope = (const float*)d_in[7];
    const float* Wk_rope = (const float*)d_in[8];
    const float* Wo      = (const float*)d_in[9];
    float* out = (float*)d_out;

    __half *ph16, *pWT, *pWkT, *pWvT, *pWoT, *pqkv, *pk, *pvt, *pao;
    cudaGetSymbolAddress((void**)&ph16, g_h16);
    cudaGetSymbolAddress((void**)&pWT,  g_WqkvT);
    cudaGetSymbolAddress((void**)&pWkT, g_WkT);
    cudaGetSymbolAddress((void**)&pWvT, g_WvT);
    cudaGetSymbolAddress((void**)&pWoT, g_WoT);
    cudaGetSymbolAddress((void**)&pqkv, g_qkv16);
    cudaGetSymbolAddress((void**)&pk,   g_k16);
    cudaGetSymbolAddress((void**)&pvt,  g_vt16);
    cudaGetSymbolAddress((void**)&pao,  g_ao16);

    static int attr_done = 0;
    if (!attr_done) {
        cudaFuncSetAttribute(gemm_h,
            cudaFuncAttributeMaxDynamicSharedMemorySize, G_SMEM_BYTES);
        cudaFuncSetAttribute(gemm_kv,
            cudaFuncAttributeMaxDynamicSharedMemorySize, G_SMEM_BYTES);
        cudaFuncSetAttribute(flash_attn_h,
            cudaFuncAttributeMaxDynamicSharedMemorySize, FA_SMEM_BYTES);
        attr_done = 1;
    }

    dim3 blk(256);
    // launch 0: prepass (h cvt + all weight transposes)
    prepass_all<<<20480, dim3(32, 8)>>>(h, Wq, Wq_rope, Wkv, Wk_up, Wk_rope,
                                        Wv_up, Wo, ph16, pWT, pWkT, pWvT, pWoT);

    // launch 1: qkv = fp16(h @ [Wq_eff*s | Wkv])
    gemm_h<<<dim3(QKV_N / GBN, ROWS / GBM), blk, G_SMEM_BYTES>>>(
        ROWS, QKV_N, HIDDEN, ph16, HIDDEN, pWT, HIDDEN, pqkv, QKV_N, 1.f, 1);

    // launch 2: k AND v^T in one launch (grid.z)
    gemm_kv<<<dim3(HIDDEN / GBN, ROWS / GBM, 2), blk, G_SMEM_BYTES>>>(
        pqkv, pWkT, pWvT, pk, pvt);

    // launch 3: attention — Br=64, 128 threads, 2 CTAs/SM
    flash_attn_h<<<dim3(S_LEN / 64, BATCH * NHEADS), 128, FA_SMEM_BYTES>>>(
        pqkv, pk, pvt, pao);

    // launch 4: out = fp32(ao @ Wo)
    gemm_h<<<dim3(HIDDEN / GBN, ROWS / GBM), blk, G_SMEM_BYTES>>>(
        ROWS, HIDDEN, HIDDEN, pao, HIDDEN, pWoT, HIDDEN, out, HIDDEN, 1.f, 0);
}

// round 15
// speedup vs baseline: 1.1851x; 1.0761x over previous
#include <cuda_runtime.h>
#include <cuda_fp16.h>
#include <cstdint>

// ---------------- problem constants ----------------
#define S_LEN  2048
#define HIDDEN 2048
#define NHEADS 16
#define HD     128
#define LATENT 512
#define BATCH  2
#define ROWS   (BATCH * S_LEN)           // 4096
#define QK_SCALE 0.12751745f             // 128^-0.5 * log2(e)
#define QKV_N  (HIDDEN + 2 * LATENT)     // 3072

// ---------------- scratch ----------------
static __device__ __half g_h16  [(size_t)ROWS * HIDDEN];
static __device__ __half g_WqkvT[(size_t)QKV_N * HIDDEN];
static __device__ __half g_WkT  [(size_t)HIDDEN * LATENT];
static __device__ __half g_WvT  [(size_t)HIDDEN * LATENT];
static __device__ __half g_WoT  [(size_t)HIDDEN * HIDDEN];
static __device__ __half g_qkv16[(size_t)ROWS * QKV_N];
static __device__ __half g_k16  [(size_t)ROWS * HIDDEN];
static __device__ __half g_vt16 [(size_t)HIDDEN * ROWS];
static __device__ __half g_ao16 [(size_t)ROWS * HIDDEN];

// ---------------- asm helpers ----------------
__device__ __forceinline__ void mma_h(float* c, const uint32_t* a,
                                      uint32_t b0, uint32_t b1) {
    asm volatile(
        "mma.sync.aligned.m16n8k16.row.col.f32.f16.f16.f32 "
        "{%0,%1,%2,%3}, {%4,%5,%6,%7}, {%8,%9}, {%0,%1,%2,%3};"
        : "+f"(c[0]), "+f"(c[1]), "+f"(c[2]), "+f"(c[3])
        : "r"(a[0]), "r"(a[1]), "r"(a[2]), "r"(a[3]), "r"(b0), "r"(b1));
}
__device__ __forceinline__ void ldsm_x4(uint32_t& r0, uint32_t& r1,
                                        uint32_t& r2, uint32_t& r3,
                                        uint32_t addr) {
    asm volatile("ldmatrix.sync.aligned.m8n8.x4.shared.b16 {%0,%1,%2,%3}, [%4];"
                 : "=r"(r0), "=r"(r1), "=r"(r2), "=r"(r3) : "r"(addr));
}
__device__ __forceinline__ void cp16(uint32_t dst, const void* src) {
    asm volatile("cp.async.cg.shared.global [%0], [%1], 16;" :: "r"(dst), "l"(src));
}
__device__ __forceinline__ void cp_commit() {
    asm volatile("cp.async.commit_group;");
}
__device__ __forceinline__ void cp_wait1() {
    asm volatile("cp.async.wait_group 1;");
}
__device__ __forceinline__ void cp_wait2() {
    asm volatile("cp.async.wait_group 2;");
}
__device__ __forceinline__ uint32_t h2pack(float hi, float lo) {
    uint32_t r;
    asm("cvt.rn.f16x2.f32 %0, %1, %2;" : "=r"(r) : "f"(hi), "f"(lo));
    return r;
}
// raw MUFU.EX2 (error <= 2^-22 rel; skips libm fixup code)
__device__ __forceinline__ float ex2(float x) {
    float y;
    asm("ex2.approx.ftz.f32 %0, %1;" : "=f"(y) : "f"(x));
    return y;
}

// ---------------- pre-pass: ONE launch (h cvt + all weight transposes) ----
__global__ void prepass_all(const float* __restrict__ hsrc,
                            const float* __restrict__ Wq,
                            const float* __restrict__ Wq_rope,
                            const float* __restrict__ Wkv,
                            const float* __restrict__ Wk_up,
                            const float* __restrict__ Wk_rope,
                            const float* __restrict__ Wv_up,
                            const float* __restrict__ Wo,
                            __half* __restrict__ ph16,
                            __half* __restrict__ pWT,
                            __half* __restrict__ pWkT,
                            __half* __restrict__ pWvT,
                            __half* __restrict__ pWoT)
{
    int bid = blockIdx.x;
    int tid = threadIdx.y * 32 + threadIdx.x;

    if (bid >= 12288) {                 // h -> fp16 segment
        int idx = (bid - 12288) * 1024 + tid * 4;
        float4 v = *(const float4*)(hsrc + idx);
        __half2* p = (__half2*)(ph16 + idx);
        p[0] = __floats2half2_rn(v.x, v.y);
        p[1] = __floats2half2_rn(v.z, v.w);
        return;
    }

    __shared__ float t[32][33];
    const float *a, *a2 = nullptr;
    __half* o;
    int K, N, nbx;
    float scale = 1.f;
    if (bid < 4096)      { a = Wq;    a2 = Wq_rope; o = pWT;  K = 2048; N = 2048; nbx = 64; scale = QK_SCALE; }
    else if (bid < 6144) { bid -= 4096; a = Wkv;    o = pWT + (size_t)HIDDEN * HIDDEN; K = 2048; N = 1024; nbx = 32; }
    else if (bid < 7168) { bid -= 6144; a = Wk_up;  a2 = Wk_rope; o = pWkT; K = 512; N = 2048; nbx = 64; }
    else if (bid < 8192) { bid -= 7168; a = Wv_up;  o = pWvT; K = 512;  N = 2048; nbx = 64; }
    else                 { bid -= 8192; a = Wo;     o = pWoT; K = 2048; N = 2048; nbx = 64; }
    int n0 = (bid % nbx) * 32, k0 = (bid / nbx) * 32;
    int x = threadIdx.x, y = threadIdx.y;
#pragma unroll
    for (int i = 0; i < 4; i++) {
        int k = k0 + y + 8 * i;
        float v = a[(size_t)k * N + n0 + x];
        if (a2) v += a2[(size_t)k * N + n0 + x];
        t[y + 8 * i][x] = v;
    }
    __syncthreads();
#pragma unroll
    for (int i = 0; i < 4; i++) {
        int n = n0 + y + 8 * i;
        o[(size_t)n * K + k0 + x] = __float2half_rn(t[x][y + 8 * i] * scale);
    }
}

// =======================================================================
// fp16 mma.sync GEMM body (round-11 exact): 128x128, BK=32, 4-stage
// cp.async, 2 CTAs/SM, warp tile 32x64.
// =======================================================================
#define GBM 128
#define GBN 128
#define GBK 32
#define ALD 40
#define BLD 40
#define STG_A (GBM * ALD)
#define STG_B (GBN * BLD)
#define STG_SZ (STG_A + STG_B)
#define G_NSTG 4
#define G_SMEM_BYTES (G_NSTG * STG_SZ * 2)

__device__ __forceinline__
void gemm_body(int K,
               const __half* __restrict__ A, int lda,
               const __half* __restrict__ Bt, int ldb,
               void* __restrict__ C, int ldc,
               float scale, int mode,
               int bm, int bn, __half* gsm)
{
    const int tid = threadIdx.x, lane = tid & 31, wid = tid >> 5;
    const int gid = lane >> 2, t4 = lane & 3;
    const int wm = wid >> 1, wn = wid & 1;
    const uint32_t sbase = (uint32_t)__cvta_generic_to_shared(gsm);

    const int ar = tid >> 2;
    const int ac = (tid & 3) * 8;

    auto load_stage = [&](int kt, int stg) {
        const __half* Ag = A + (size_t)bm * lda + kt * GBK;
        uint32_t as = sbase + stg * STG_SZ * 2;
#pragma unroll
        for (int i = 0; i < 2; i++) {
            int r = ar + 64 * i;
            cp16(as + (r * ALD + ac) * 2, Ag + (size_t)r * lda + ac);
        }
        const __half* Bg = Bt + (size_t)bn * ldb + kt * GBK;
        uint32_t bs = sbase + (stg * STG_SZ + STG_A) * 2;
#pragma unroll
        for (int i = 0; i < 2; i++) {
            int r = ar + 64 * i;
            cp16(bs + (r * BLD + ac) * 2, Bg + (size_t)r * ldb + ac);
        }
        cp_commit();
    };

    float acc[2][8][4];
#pragma unroll
    for (int mi = 0; mi < 2; mi++)
#pragma unroll
        for (int ni = 0; ni < 8; ni++)
#pragma unroll
            for (int x = 0; x < 4; x++) acc[mi][ni][x] = 0.f;

    const int nk = K / GBK;
    load_stage(0, 0);
    load_stage(1, 1);
    load_stage(2, 2);

    const int arow = (lane & 7) + 8 * ((lane >> 3) & 1);
    const int acol = 8 * (lane >> 4);
    const int brow = lane & 7;
    const int bcol = 8 * (lane >> 3);

    for (int kt = 0; kt < nk; kt++) {
        cp_wait2();
        __syncthreads();
        if (kt + 3 < nk) load_stage(kt + 3, (kt + 3) % G_NSTG);
        else cp_commit();

        const int stg = kt % G_NSTG;
        const uint32_t as = sbase + stg * STG_SZ * 2;
        const uint32_t bs = sbase + (stg * STG_SZ + STG_A) * 2;

        uint32_t bf[8][4];
#pragma unroll
        for (int ni = 0; ni < 8; ni++) {
            int n0 = wn * 64 + ni * 8;
            ldsm_x4(bf[ni][0], bf[ni][1], bf[ni][2], bf[ni][3],
                    bs + ((n0 + brow) * BLD + bcol) * 2);
        }
#pragma unroll
        for (int ks = 0; ks < 2; ks++) {
            uint32_t af[2][4];
#pragma unroll
            for (int mi = 0; mi < 2; mi++) {
                int m0 = wm * 32 + mi * 16;
                ldsm_x4(af[mi][0], af[mi][1], af[mi][2], af[mi][3],
                        as + ((m0 + arow) * ALD + ks * 16 + acol) * 2);
            }
#pragma unroll
            for (int ni = 0; ni < 8; ni++)
#pragma unroll
                for (int mi = 0; mi < 2; mi++)
                    mma_h(acc[mi][ni], af[mi], bf[ni][ks * 2], bf[ni][ks * 2 + 1]);
        }
    }

#pragma unroll
    for (int mi = 0; mi < 2; mi++) {
        int row = bm + wm * 32 + mi * 16 + gid;
#pragma unroll
        for (int ni = 0; ni < 8; ni++) {
            int col = bn + wn * 64 + ni * 8 + 2 * t4;
            float v0 = acc[mi][ni][0] * scale;
            float v1 = acc[mi][ni][1] * scale;
            float v2 = acc[mi][ni][2] * scale;
            float v3 = acc[mi][ni][3] * scale;
            if (mode == 0) {
                float* Cf = (float*)C;
                *(float2*)(Cf + (size_t)row * ldc + col)       = make_float2(v0, v1);
                *(float2*)(Cf + (size_t)(row + 8) * ldc + col) = make_float2(v2, v3);
            } else if (mode == 1) {
                __half* Ch = (__half*)C;
                *(__half2*)(Ch + (size_t)row * ldc + col)       = __floats2half2_rn(v0, v1);
                *(__half2*)(Ch + (size_t)(row + 8) * ldc + col) = __floats2half2_rn(v2, v3);
            } else {
                __half* Ch = (__half*)C;      // [N][M], ldc = M
                Ch[(size_t)col * ldc + row]           = __float2half_rn(v0);
                Ch[(size_t)(col + 1) * ldc + row]     = __float2half_rn(v1);
                Ch[(size_t)col * ldc + row + 8]       = __float2half_rn(v2);
                Ch[(size_t)(col + 1) * ldc + row + 8] = __float2half_rn(v3);
            }
        }
    }
}

__global__ __launch_bounds__(256, 2)
void gemm_h(int M, int N, int K,
            const __half* __restrict__ A, int lda,
            const __half* __restrict__ Bt, int ldb,
            void* __restrict__ C, int ldc,
            float scale, int mode)
{
    extern __shared__ __half gsm[];
    gemm_body(K, A, lda, Bt, ldb, C, ldc, scale, mode,
              blockIdx.y * GBM, blockIdx.x * GBN, gsm);
}

__global__ __launch_bounds__(256, 2)
void gemm_kv(const __half* __restrict__ qkv,
             const __half* __restrict__ WkT,
             const __half* __restrict__ WvT,
             __half* __restrict__ Ck,
             __half* __restrict__ Cvt)
{
    extern __shared__ __half gsm[];
    if (blockIdx.z == 0) {
        gemm_body(LATENT, qkv + HIDDEN, QKV_N, WkT, LATENT, Ck, HIDDEN,
                  1.f, 1, blockIdx.y * GBM, blockIdx.x * GBN, gsm);
    } else {
        gemm_body(LATENT, qkv + HIDDEN + LATENT, QKV_N, WvT, LATENT, Cvt, ROWS,
                  1.f, 2, blockIdx.y * GBM, blockIdx.x * GBN, gsm);
    }
}

// =======================================================================
// fp16 flash attention — round-11 version (best measured: 144us) with
// exp2f -> raw ex2.approx. 128 thr, Br=64, Bc=64, 2 CTAs/SM,
// 2-stage ring, Q frags persistent.
// =======================================================================
#define QLDH 136
#define KLDH 136
#define VLDH 72
#define Q_SZ   (64 * QLDH)
#define K_STG  (64 * KLDH)
#define V_STG  (128 * VLDH)
#define K_OFF  Q_SZ
#define V_OFF  (Q_SZ + 2 * K_STG)
#define FA_SMEM_BYTES ((Q_SZ + 2 * (K_STG + V_STG)) * 2)   // 89088

__global__ __launch_bounds__(128)
void flash_attn_h(const __half* __restrict__ Qg,      // packed qkv, ld = 3072
                  const __half* __restrict__ Kg,
                  const __half* __restrict__ Vtg,     // [2048][4096]
                  __half* __restrict__ Og)
{
    extern __shared__ __half fsm[];
    const uint32_t sb = (uint32_t)__cvta_generic_to_shared(fsm);

    const int qt   = (gridDim.x - 1) - blockIdx.x;
    const int bh   = blockIdx.y;
    const int b    = bh >> 4;
    const int h    = bh & 15;
    const int tid  = threadIdx.x;
    const int lane = tid & 31;
    const int wid  = tid >> 5;
    const int gid  = lane >> 2;
    const int t4   = lane & 3;

    {
        const __half* qb = Qg + (size_t)(b * S_LEN + qt * 64) * QKV_N + h * HD;
#pragma unroll
        for (int i = 0; i < 8; i++) {
            int g = tid + 128 * i;
            int r = g >> 4, c = (g & 15) * 8;
            cp16(sb + (r * QLDH + c) * 2, qb + (size_t)r * QKV_N + c);
        }
        cp_commit();
    }

    auto load_kv = [&](int kt, int stg) {
        const __half* kb = Kg + (size_t)(b * S_LEN + kt * 64) * HIDDEN + h * HD;
        uint32_t ks = sb + (K_OFF + stg * K_STG) * 2;
#pragma unroll
        for (int i = 0; i < 8; i++) {
            int g = tid + 128 * i;
            int r = g >> 4, c = (g & 15) * 8;
            cp16(ks + (r * KLDH + c) * 2, kb + (size_t)r * HIDDEN + c);
        }
        const __half* vb = Vtg + (size_t)(h * HD) * ROWS + b * S_LEN + kt * 64;
        uint32_t vs = sb + (V_OFF + stg * V_STG) * 2;
#pragma unroll
        for (int i = 0; i < 8; i++) {
            int g = tid + 128 * i;
            int r = g >> 3, c = (g & 7) * 8;
            cp16(vs + (r * VLDH + c) * 2, vb + (size_t)r * ROWS + c);
        }
        cp_commit();
    };

    const int nkt = qt + 1;
    load_kv(0, 0);

    const int arow = (lane & 7) + 8 * ((lane >> 3) & 1);
    const int acol = 8 * (lane >> 4);
    const int brow = lane & 7;
    const int bcol = 8 * (lane >> 3);
    const int r0 = wid * 16;

    uint32_t q[8][4];
    cp_wait1();
    __syncthreads();
#pragma unroll
    for (int ks = 0; ks < 8; ks++)
        ldsm_x4(q[ks][0], q[ks][1], q[ks][2], q[ks][3],
                sb + ((r0 + arow) * QLDH + ks * 16 + acol) * 2);

    float o[16][4];
#pragma unroll
    for (int ni = 0; ni < 16; ni++)
#pragma unroll
        for (int x = 0; x < 4; x++) o[ni][x] = 0.f;
    float m_lo = -1e30f, m_hi = -1e30f, l_lo = 0.f, l_hi = 0.f;

    const int row_lo = qt * 64 + r0 + gid;
    const int row_hi = row_lo + 8;

    for (int kt = 0; kt < nkt; kt++) {
        const int stg = kt & 1;
        __syncthreads();
        if (kt + 1 < nkt) load_kv(kt + 1, stg ^ 1);
        else cp_commit();
        cp_wait1();
        __syncthreads();

        const uint32_t ksb = sb + (K_OFF + stg * K_STG) * 2;
        const uint32_t vsb = sb + (V_OFF + stg * V_STG) * 2;

        float s[8][4];
#pragma unroll
        for (int ni = 0; ni < 8; ni++)
#pragma unroll
            for (int x = 0; x < 4; x++) s[ni][x] = 0.f;

#pragma unroll
        for (int kc = 0; kc < 4; kc++) {
#pragma unroll
            for (int ni = 0; ni < 8; ni++) {
                uint32_t kb4[4];
                ldsm_x4(kb4[0], kb4[1], kb4[2], kb4[3],
                        ksb + ((ni * 8 + brow) * KLDH + kc * 32 + bcol) * 2);
                mma_h(s[ni], q[kc * 2],     kb4[0], kb4[1]);
                mma_h(s[ni], q[kc * 2 + 1], kb4[2], kb4[3]);
            }
        }

        if (kt == qt) {
            const int cb = kt * 64 + 2 * t4;
#pragma unroll
            for (int ni = 0; ni < 8; ni++) {
                int c0 = cb + ni * 8;
                if (c0     > row_lo) s[ni][0] = -1e30f;
                if (c0 + 1 > row_lo) s[ni][1] = -1e30f;
                if (c0     > row_hi) s[ni][2] = -1e30f;
                if (c0 + 1 > row_hi) s[ni][3] = -1e30f;
            }
        }

        float mlo = -1e30f, mhi = -1e30f;
#pragma unroll
        for (int ni = 0; ni < 8; ni++) {
            mlo = fmaxf(mlo, fmaxf(s[ni][0], s[ni][1]));
            mhi = fmaxf(mhi, fmaxf(s[ni][2], s[ni][3]));
        }
        mlo = fmaxf(mlo, __shfl_xor_sync(0xffffffffu, mlo, 1));
        mlo = fmaxf(mlo, __shfl_xor_sync(0xffffffffu, mlo, 2));
        mhi = fmaxf(mhi, __shfl_xor_sync(0xffffffffu, mhi, 1));
        mhi = fmaxf(mhi, __shfl_xor_sync(0xffffffffu, mhi, 2));

        float mnl = fmaxf(m_lo, mlo), mnh = fmaxf(m_hi, mhi);
        float clo = ex2(m_lo - mnl), chi = ex2(m_hi - mnh);
        m_lo = mnl; m_hi = mnh;

        float rlo = 0.f, rhi = 0.f;
#pragma unroll
        for (int ni = 0; ni < 8; ni++) {
            s[ni][0] = ex2(s[ni][0] - mnl);
            s[ni][1] = ex2(s[ni][1] - mnl);
            s[ni][2] = ex2(s[ni][2] - mnh);
            s[ni][3] = ex2(s[ni][3] - mnh);
            rlo += s[ni][0] + s[ni][1];
            rhi += s[ni][2] + s[ni][3];
        }
        rlo += __shfl_xor_sync(0xffffffffu, rlo, 1);
        rlo += __shfl_xor_sync(0xffffffffu, rlo, 2);
        rhi += __shfl_xor_sync(0xffffffffu, rhi, 1);
        rhi += __shfl_xor_sync(0xffffffffu, rhi, 2);
        l_lo = l_lo * clo + rlo;
        l_hi = l_hi * chi + rhi;

#pragma unroll
        for (int ni = 0; ni < 16; ni++) {
            o[ni][0] *= clo; o[ni][1] *= clo;
            o[ni][2] *= chi; o[ni][3] *= chi;
        }

        uint32_t pa[4][4];
#pragma unroll
        for (int kc = 0; kc < 4; kc++) {
            pa[kc][0] = h2pack(s[2 * kc][1],     s[2 * kc][0]);
            pa[kc][1] = h2pack(s[2 * kc][3],     s[2 * kc][2]);
            pa[kc][2] = h2pack(s[2 * kc + 1][1], s[2 * kc + 1][0]);
            pa[kc][3] = h2pack(s[2 * kc + 1][3], s[2 * kc + 1][2]);
        }

#pragma unroll
        for (int vc = 0; vc < 2; vc++) {
#pragma unroll
            for (int ni = 0; ni < 16; ni++) {
                uint32_t vb4[4];
                ldsm_x4(vb4[0], vb4[1], vb4[2], vb4[3],
                        vsb + ((ni * 8 + brow) * VLDH + vc * 32 + bcol) * 2);
                mma_h(o[ni], pa[vc * 2],     vb4[0], vb4[1]);
                mma_h(o[ni], pa[vc * 2 + 1], vb4[2], vb4[3]);
            }
        }
    }

    const float il0 = 1.f / l_lo, il1 = 1.f / l_hi;
    __half* olo = Og + (size_t)(b * S_LEN + row_lo) * HIDDEN + h * HD;
    __half* ohi = Og + (size_t)(b * S_LEN + row_hi) * HIDDEN + h * HD;
#pragma unroll
    for (int ni = 0; ni < 16; ni++) {
        int col = ni * 8 + 2 * t4;
        *(__half2*)(olo + col) = __floats2half2_rn(o[ni][0] * il0, o[ni][1] * il0);
        *(__half2*)(ohi + col) = __floats2half2_rn(o[ni][2] * il1, o[ni][3] * il1);
    }
}

// ---------------- launch ----------------
extern "C" void kernel_launch(void* const* d_in, const int* in_sizes, int n_in,
                              void* d_out, int out_size)
{
    const float* h       = (const float*)d_in[0];
    const float* Wq      = (const float*)d_in[3];
    const float* Wkv     = (const float*)d_in[4];
    const float* Wk_up   = (const float*)d_in[5];
    const float* Wv_up   = (const float*)d_in[6];
    const float* Wq_rope = (const float*)d_in[7];
    const float* Wk_rope = (const float*)d_in[8];
    const float* Wo      = (const float*)d_in[9];
    float* out = (float*)d_out;

    __half *ph16, *pWT, *pWkT, *pWvT, *pWoT, *pqkv, *pk, *pvt, *pao;
    cudaGetSymbolAddress((void**)&ph16, g_h16);
    cudaGetSymbolAddress((void**)&pWT,  g_WqkvT);
    cudaGetSymbolAddress((void**)&pWkT, g_WkT);
    cudaGetSymbolAddress((void**)&pWvT, g_WvT);
    cudaGetSymbolAddress((void**)&pWoT, g_WoT);
    cudaGetSymbolAddress((void**)&pqkv, g_qkv16);
    cudaGetSymbolAddress((void**)&pk,   g_k16);
    cudaGetSymbolAddress((void**)&pvt,  g_vt16);
    cudaGetSymbolAddress((void**)&pao,  g_ao16);

    static int attr_done = 0;
    if (!attr_done) {
        cudaFuncSetAttribute(gemm_h,
            cudaFuncAttributeMaxDynamicSharedMemorySize, G_SMEM_BYTES);
        cudaFuncSetAttribute(gemm_kv,
            cudaFuncAttributeMaxDynamicSharedMemorySize, G_SMEM_BYTES);
        cudaFuncSetAttribute(flash_attn_h,
            cudaFuncAttributeMaxDynamicSharedMemorySize, FA_SMEM_BYTES);
        attr_done = 1;
    }

    dim3 blk(256);
    // launch 0: prepass (h cvt + all weight transposes)
    prepass_all<<<20480, dim3(32, 8)>>>(h, Wq, Wq_rope, Wkv, Wk_up, Wk_rope,
                                        Wv_up, Wo, ph16, pWT, pWkT, pWvT, pWoT);

    // launch 1: qkv = fp16(h @ [Wq_eff*s | Wkv])
    gemm_h<<<dim3(QKV_N / GBN, ROWS / GBM), blk, G_SMEM_BYTES>>>(
        ROWS, QKV_N, HIDDEN, ph16, HIDDEN, pWT, HIDDEN, pqkv, QKV_N, 1.f, 1);

    // launch 2: k AND v^T in one launch (grid.z)
    gemm_kv<<<dim3(HIDDEN / GBN, ROWS / GBM, 2), blk, G_SMEM_BYTES>>>(
        pqkv, pWkT, pWvT, pk, pvt);

    // launch 3: attention — Br=64, 128 threads, 2 CTAs/SM
    flash_attn_h<<<dim3(S_LEN / 64, BATCH * NHEADS), 128, FA_SMEM_BYTES>>>(
        pqkv, pk, pvt, pao);

    // launch 4: out = fp32(ao @ Wo)
    gemm_h<<<dim3(HIDDEN / GBN, ROWS / GBM), blk, G_SMEM_BYTES>>>(
        ROWS, HIDDEN, HIDDEN, pao, HIDDEN, pWoT, HIDDEN, out, HIDDEN, 1.f, 0);
}

// round 16
// speedup vs baseline: 1.1990x; 1.0117x over previous
#include <cuda_runtime.h>
#include <cuda_fp16.h>
#include <cstdint>

// ---------------- problem constants ----------------
#define S_LEN  2048
#define HIDDEN 2048
#define NHEADS 16
#define HD     128
#define LATENT 512
#define BATCH  2
#define ROWS   (BATCH * S_LEN)           // 4096
#define QK_SCALE 0.12751745f             // 128^-0.5 * log2(e)
#define QKV_N  (HIDDEN + 2 * LATENT)     // 3072

// ---------------- scratch ----------------
static __device__ __half g_h16  [(size_t)ROWS * HIDDEN];
static __device__ __half g_WqkvT[(size_t)QKV_N * HIDDEN];
static __device__ __half g_WkT  [(size_t)HIDDEN * LATENT];
static __device__ __half g_WvT  [(size_t)HIDDEN * LATENT];
static __device__ __half g_WoT  [(size_t)HIDDEN * HIDDEN];
static __device__ __half g_qkv16[(size_t)ROWS * QKV_N];
static __device__ __half g_k16  [(size_t)ROWS * HIDDEN];
static __device__ __half g_vt16 [(size_t)HIDDEN * ROWS];
static __device__ __half g_ao16 [(size_t)ROWS * HIDDEN];

// ---------------- asm helpers ----------------
__device__ __forceinline__ void mma_h(float* c, const uint32_t* a,
                                      uint32_t b0, uint32_t b1) {
    asm volatile(
        "mma.sync.aligned.m16n8k16.row.col.f32.f16.f16.f32 "
        "{%0,%1,%2,%3}, {%4,%5,%6,%7}, {%8,%9}, {%0,%1,%2,%3};"
        : "+f"(c[0]), "+f"(c[1]), "+f"(c[2]), "+f"(c[3])
        : "r"(a[0]), "r"(a[1]), "r"(a[2]), "r"(a[3]), "r"(b0), "r"(b1));
}
__device__ __forceinline__ void ldsm_x4(uint32_t& r0, uint32_t& r1,
                                        uint32_t& r2, uint32_t& r3,
                                        uint32_t addr) {
    asm volatile("ldmatrix.sync.aligned.m8n8.x4.shared.b16 {%0,%1,%2,%3}, [%4];"
                 : "=r"(r0), "=r"(r1), "=r"(r2), "=r"(r3) : "r"(addr));
}
__device__ __forceinline__ void cp16(uint32_t dst, const void* src) {
    asm volatile("cp.async.cg.shared.global [%0], [%1], 16;" :: "r"(dst), "l"(src));
}
__device__ __forceinline__ void cp_commit() {
    asm volatile("cp.async.commit_group;");
}
__device__ __forceinline__ void cp_wait0() {
    asm volatile("cp.async.wait_group 0;");
}
__device__ __forceinline__ void cp_wait1() {
    asm volatile("cp.async.wait_group 1;");
}
__device__ __forceinline__ void cp_wait2() {
    asm volatile("cp.async.wait_group 2;");
}
__device__ __forceinline__ uint32_t h2pack(float hi, float lo) {
    uint32_t r;
    asm("cvt.rn.f16x2.f32 %0, %1, %2;" : "=r"(r) : "f"(hi), "f"(lo));
    return r;
}
// raw MUFU.EX2 (error <= 2^-22 rel; skips libm fixup code)
__device__ __forceinline__ float ex2(float x) {
    float y;
    asm("ex2.approx.ftz.f32 %0, %1;" : "=f"(y) : "f"(x));
    return y;
}

// ---------------- pre-pass: ONE launch (h cvt + all weight transposes) ----
__global__ void prepass_all(const float* __restrict__ hsrc,
                            const float* __restrict__ Wq,
                            const float* __restrict__ Wq_rope,
                            const float* __restrict__ Wkv,
                            const float* __restrict__ Wk_up,
                            const float* __restrict__ Wk_rope,
                            const float* __restrict__ Wv_up,
                            const float* __restrict__ Wo,
                            __half* __restrict__ ph16,
                            __half* __restrict__ pWT,
                            __half* __restrict__ pWkT,
                            __half* __restrict__ pWvT,
                            __half* __restrict__ pWoT)
{
    int bid = blockIdx.x;
    int tid = threadIdx.y * 32 + threadIdx.x;

    if (bid >= 12288) {                 // h -> fp16 segment
        int idx = (bid - 12288) * 1024 + tid * 4;
        float4 v = *(const float4*)(hsrc + idx);
        __half2* p = (__half2*)(ph16 + idx);
        p[0] = __floats2half2_rn(v.x, v.y);
        p[1] = __floats2half2_rn(v.z, v.w);
        return;
    }

    __shared__ float t[32][33];
    const float *a, *a2 = nullptr;
    __half* o;
    int K, N, nbx;
    float scale = 1.f;
    if (bid < 4096)      { a = Wq;    a2 = Wq_rope; o = pWT;  K = 2048; N = 2048; nbx = 64; scale = QK_SCALE; }
    else if (bid < 6144) { bid -= 4096; a = Wkv;    o = pWT + (size_t)HIDDEN * HIDDEN; K = 2048; N = 1024; nbx = 32; }
    else if (bid < 7168) { bid -= 6144; a = Wk_up;  a2 = Wk_rope; o = pWkT; K = 512; N = 2048; nbx = 64; }
    else if (bid < 8192) { bid -= 7168; a = Wv_up;  o = pWvT; K = 512;  N = 2048; nbx = 64; }
    else                 { bid -= 8192; a = Wo;     o = pWoT; K = 2048; N = 2048; nbx = 64; }
    int n0 = (bid % nbx) * 32, k0 = (bid / nbx) * 32;
    int x = threadIdx.x, y = threadIdx.y;
#pragma unroll
    for (int i = 0; i < 4; i++) {
        int k = k0 + y + 8 * i;
        float v = a[(size_t)k * N + n0 + x];
        if (a2) v += a2[(size_t)k * N + n0 + x];
        t[y + 8 * i][x] = v;
    }
    __syncthreads();
#pragma unroll
    for (int i = 0; i < 4; i++) {
        int n = n0 + y + 8 * i;
        o[(size_t)n * K + k0 + x] = __float2half_rn(t[x][y + 8 * i] * scale);
    }
}

// =======================================================================
// fp16 mma.sync GEMM body (round-11 exact): 128x128, BK=32, 4-stage
// cp.async, 2 CTAs/SM, warp tile 32x64.
// =======================================================================
#define GBM 128
#define GBN 128
#define GBK 32
#define ALD 40
#define BLD 40
#define STG_A (GBM * ALD)
#define STG_B (GBN * BLD)
#define STG_SZ (STG_A + STG_B)
#define G_NSTG 4
#define G_SMEM_BYTES (G_NSTG * STG_SZ * 2)

__device__ __forceinline__
void gemm_body(int K,
               const __half* __restrict__ A, int lda,
               const __half* __restrict__ Bt, int ldb,
               void* __restrict__ C, int ldc,
               float scale, int mode,
               int bm, int bn, __half* gsm)
{
    const int tid = threadIdx.x, lane = tid & 31, wid = tid >> 5;
    const int gid = lane >> 2, t4 = lane & 3;
    const int wm = wid >> 1, wn = wid & 1;
    const uint32_t sbase = (uint32_t)__cvta_generic_to_shared(gsm);

    const int ar = tid >> 2;
    const int ac = (tid & 3) * 8;

    auto load_stage = [&](int kt, int stg) {
        const __half* Ag = A + (size_t)bm * lda + kt * GBK;
        uint32_t as = sbase + stg * STG_SZ * 2;
#pragma unroll
        for (int i = 0; i < 2; i++) {
            int r = ar + 64 * i;
            cp16(as + (r * ALD + ac) * 2, Ag + (size_t)r * lda + ac);
        }
        const __half* Bg = Bt + (size_t)bn * ldb + kt * GBK;
        uint32_t bs = sbase + (stg * STG_SZ + STG_A) * 2;
#pragma unroll
        for (int i = 0; i < 2; i++) {
            int r = ar + 64 * i;
            cp16(bs + (r * BLD + ac) * 2, Bg + (size_t)r * ldb + ac);
        }
        cp_commit();
    };

    float acc[2][8][4];
#pragma unroll
    for (int mi = 0; mi < 2; mi++)
#pragma unroll
        for (int ni = 0; ni < 8; ni++)
#pragma unroll
            for (int x = 0; x < 4; x++) acc[mi][ni][x] = 0.f;

    const int nk = K / GBK;
    load_stage(0, 0);
    load_stage(1, 1);
    load_stage(2, 2);

    const int arow = (lane & 7) + 8 * ((lane >> 3) & 1);
    const int acol = 8 * (lane >> 4);
    const int brow = lane & 7;
    const int bcol = 8 * (lane >> 3);

    for (int kt = 0; kt < nk; kt++) {
        cp_wait2();
        __syncthreads();
        if (kt + 3 < nk) load_stage(kt + 3, (kt + 3) % G_NSTG);
        else cp_commit();

        const int stg = kt % G_NSTG;
        const uint32_t as = sbase + stg * STG_SZ * 2;
        const uint32_t bs = sbase + (stg * STG_SZ + STG_A) * 2;

        uint32_t bf[8][4];
#pragma unroll
        for (int ni = 0; ni < 8; ni++) {
            int n0 = wn * 64 + ni * 8;
            ldsm_x4(bf[ni][0], bf[ni][1], bf[ni][2], bf[ni][3],
                    bs + ((n0 + brow) * BLD + bcol) * 2);
        }
#pragma unroll
        for (int ks = 0; ks < 2; ks++) {
            uint32_t af[2][4];
#pragma unroll
            for (int mi = 0; mi < 2; mi++) {
                int m0 = wm * 32 + mi * 16;
                ldsm_x4(af[mi][0], af[mi][1], af[mi][2], af[mi][3],
                        as + ((m0 + arow) * ALD + ks * 16 + acol) * 2);
            }
#pragma unroll
            for (int ni = 0; ni < 8; ni++)
#pragma unroll
                for (int mi = 0; mi < 2; mi++)
                    mma_h(acc[mi][ni], af[mi], bf[ni][ks * 2], bf[ni][ks * 2 + 1]);
        }
    }

#pragma unroll
    for (int mi = 0; mi < 2; mi++) {
        int row = bm + wm * 32 + mi * 16 + gid;
#pragma unroll
        for (int ni = 0; ni < 8; ni++) {
            int col = bn + wn * 64 + ni * 8 + 2 * t4;
            float v0 = acc[mi][ni][0] * scale;
            float v1 = acc[mi][ni][1] * scale;
            float v2 = acc[mi][ni][2] * scale;
            float v3 = acc[mi][ni][3] * scale;
            if (mode == 0) {
                float* Cf = (float*)C;
                *(float2*)(Cf + (size_t)row * ldc + col)       = make_float2(v0, v1);
                *(float2*)(Cf + (size_t)(row + 8) * ldc + col) = make_float2(v2, v3);
            } else if (mode == 1) {
                __half* Ch = (__half*)C;
                *(__half2*)(Ch + (size_t)row * ldc + col)       = __floats2half2_rn(v0, v1);
                *(__half2*)(Ch + (size_t)(row + 8) * ldc + col) = __floats2half2_rn(v2, v3);
            } else {
                __half* Ch = (__half*)C;      // [N][M], ldc = M
                Ch[(size_t)col * ldc + row]           = __float2half_rn(v0);
                Ch[(size_t)(col + 1) * ldc + row]     = __float2half_rn(v1);
                Ch[(size_t)col * ldc + row + 8]       = __float2half_rn(v2);
                Ch[(size_t)(col + 1) * ldc + row + 8] = __float2half_rn(v3);
            }
        }
    }
}

__global__ __launch_bounds__(256, 2)
void gemm_h(int M, int N, int K,
            const __half* __restrict__ A, int lda,
            const __half* __restrict__ Bt, int ldb,
            void* __restrict__ C, int ldc,
            float scale, int mode)
{
    extern __shared__ __half gsm[];
    gemm_body(K, A, lda, Bt, ldb, C, ldc, scale, mode,
              blockIdx.y * GBM, blockIdx.x * GBN, gsm);
}

__global__ __launch_bounds__(256, 2)
void gemm_kv(const __half* __restrict__ qkv,
             const __half* __restrict__ WkT,
             const __half* __restrict__ WvT,
             __half* __restrict__ Ck,
             __half* __restrict__ Cvt)
{
    extern __shared__ __half gsm[];
    if (blockIdx.z == 0) {
        gemm_body(LATENT, qkv + HIDDEN, QKV_N, WkT, LATENT, Ck, HIDDEN,
                  1.f, 1, blockIdx.y * GBM, blockIdx.x * GBN, gsm);
    } else {
        gemm_body(LATENT, qkv + HIDDEN + LATENT, QKV_N, WvT, LATENT, Cvt, ROWS,
                  1.f, 2, blockIdx.y * GBM, blockIdx.x * GBN, gsm);
    }
}

// =======================================================================
// fp16 flash attention — round-15 base, two safe serial-path cuts:
//  * single barrier per tile (load issued AFTER the barrier; 2-stage reuse
//    is race-free because all warps provably finished the prior compute)
//  * l kept as per-thread partial; quad-sum deferred to after the loop
// 128 thr, Br=64, Bc=64, 2 CTAs/SM, 2-stage ring, Q frags persistent.
// =======================================================================
#define QLDH 136
#define KLDH 136
#define VLDH 72
#define Q_SZ   (64 * QLDH)
#define K_STG  (64 * KLDH)
#define V_STG  (128 * VLDH)
#define K_OFF  Q_SZ
#define V_OFF  (Q_SZ + 2 * K_STG)
#define FA_SMEM_BYTES ((Q_SZ + 2 * (K_STG + V_STG)) * 2)   // 89088

__global__ __launch_bounds__(128)
void flash_attn_h(const __half* __restrict__ Qg,      // packed qkv, ld = 3072
                  const __half* __restrict__ Kg,
                  const __half* __restrict__ Vtg,     // [2048][4096]
                  __half* __restrict__ Og)
{
    extern __shared__ __half fsm[];
    const uint32_t sb = (uint32_t)__cvta_generic_to_shared(fsm);

    const int qt   = (gridDim.x - 1) - blockIdx.x;
    const int bh   = blockIdx.y;
    const int b    = bh >> 4;
    const int h    = bh & 15;
    const int tid  = threadIdx.x;
    const int lane = tid & 31;
    const int wid  = tid >> 5;
    const int gid  = lane >> 2;
    const int t4   = lane & 3;

    {
        const __half* qb = Qg + (size_t)(b * S_LEN + qt * 64) * QKV_N + h * HD;
#pragma unroll
        for (int i = 0; i < 8; i++) {
            int g = tid + 128 * i;
            int r = g >> 4, c = (g & 15) * 8;
            cp16(sb + (r * QLDH + c) * 2, qb + (size_t)r * QKV_N + c);
        }
        cp_commit();
    }

    auto load_kv = [&](int kt, int stg) {
        const __half* kb = Kg + (size_t)(b * S_LEN + kt * 64) * HIDDEN + h * HD;
        uint32_t ks = sb + (K_OFF + stg * K_STG) * 2;
#pragma unroll
        for (int i = 0; i < 8; i++) {
            int g = tid + 128 * i;
            int r = g >> 4, c = (g & 15) * 8;
            cp16(ks + (r * KLDH + c) * 2, kb + (size_t)r * HIDDEN + c);
        }
        const __half* vb = Vtg + (size_t)(h * HD) * ROWS + b * S_LEN + kt * 64;
        uint32_t vs = sb + (V_OFF + stg * V_STG) * 2;
#pragma unroll
        for (int i = 0; i < 8; i++) {
            int g = tid + 128 * i;
            int r = g >> 3, c = (g & 7) * 8;
            cp16(vs + (r * VLDH + c) * 2, vb + (size_t)r * ROWS + c);
        }
        cp_commit();
    };

    const int nkt = qt + 1;
    load_kv(0, 0);                      // group: tile 0

    const int arow = (lane & 7) + 8 * ((lane >> 3) & 1);
    const int acol = 8 * (lane >> 4);
    const int brow = lane & 7;
    const int bcol = 8 * (lane >> 3);
    const int r0 = wid * 16;

    // Q fragments once (Q group done when <=1 group outstanding)
    uint32_t q[8][4];
    cp_wait1();
    __syncthreads();
#pragma unroll
    for (int ks = 0; ks < 8; ks++)
        ldsm_x4(q[ks][0], q[ks][1], q[ks][2], q[ks][3],
                sb + ((r0 + arow) * QLDH + ks * 16 + acol) * 2);

    float o[16][4];
#pragma unroll
    for (int ni = 0; ni < 16; ni++)
#pragma unroll
        for (int x = 0; x < 4; x++) o[ni][x] = 0.f;
    float m_lo = -1e30f, m_hi = -1e30f;
    float l_lo = 0.f, l_hi = 0.f;       // per-thread partials (quad-sum deferred)

    const int row_lo = qt * 64 + r0 + gid;
    const int row_hi = row_lo + 8;

    for (int kt = 0; kt < nkt; kt++) {
        const int stg = kt & 1;
        cp_wait0();                     // tile kt copies done (all groups)
        __syncthreads();                // visibility + all warps past compute kt-1
        if (kt + 1 < nkt) load_kv(kt + 1, stg ^ 1);   // safe: post-barrier

        const uint32_t ksb = sb + (K_OFF + stg * K_STG) * 2;
        const uint32_t vsb = sb + (V_OFF + stg * V_STG) * 2;

        float s[8][4];
#pragma unroll
        for (int ni = 0; ni < 8; ni++)
#pragma unroll
            for (int x = 0; x < 4; x++) s[ni][x] = 0.f;

#pragma unroll
        for (int kc = 0; kc < 4; kc++) {
#pragma unroll
            for (int ni = 0; ni < 8; ni++) {
                uint32_t kb4[4];
                ldsm_x4(kb4[0], kb4[1], kb4[2], kb4[3],
                        ksb + ((ni * 8 + brow) * KLDH + kc * 32 + bcol) * 2);
                mma_h(s[ni], q[kc * 2],     kb4[0], kb4[1]);
                mma_h(s[ni], q[kc * 2 + 1], kb4[2], kb4[3]);
            }
        }

        if (kt == qt) {
            const int cb = kt * 64 + 2 * t4;
#pragma unroll
            for (int ni = 0; ni < 8; ni++) {
                int c0 = cb + ni * 8;
                if (c0     > row_lo) s[ni][0] = -1e30f;
                if (c0 + 1 > row_lo) s[ni][1] = -1e30f;
                if (c0     > row_hi) s[ni][2] = -1e30f;
                if (c0 + 1 > row_hi) s[ni][3] = -1e30f;
            }
        }

        float mlo = -1e30f, mhi = -1e30f;
#pragma unroll
        for (int ni = 0; ni < 8; ni++) {
            mlo = fmaxf(mlo, fmaxf(s[ni][0], s[ni][1]));
            mhi = fmaxf(mhi, fmaxf(s[ni][2], s[ni][3]));
        }
        mlo = fmaxf(mlo, __shfl_xor_sync(0xffffffffu, mlo, 1));
        mlo = fmaxf(mlo, __shfl_xor_sync(0xffffffffu, mlo, 2));
        mhi = fmaxf(mhi, __shfl_xor_sync(0xffffffffu, mhi, 1));
        mhi = fmaxf(mhi, __shfl_xor_sync(0xffffffffu, mhi, 2));

        float mnl = fmaxf(m_lo, mlo), mnh = fmaxf(m_hi, mhi);
        float clo = ex2(m_lo - mnl), chi = ex2(m_hi - mnh);
        m_lo = mnl; m_hi = mnh;

        float rlo = 0.f, rhi = 0.f;
#pragma unroll
        for (int ni = 0; ni < 8; ni++) {
            s[ni][0] = ex2(s[ni][0] - mnl);
            s[ni][1] = ex2(s[ni][1] - mnl);
            s[ni][2] = ex2(s[ni][2] - mnh);
            s[ni][3] = ex2(s[ni][3] - mnh);
            rlo += s[ni][0] + s[ni][1];
            rhi += s[ni][2] + s[ni][3];
        }
        // per-thread partial; quad-reduction deferred to after the loop
        l_lo = l_lo * clo + rlo;
        l_hi = l_hi * chi + rhi;

#pragma unroll
        for (int ni = 0; ni < 16; ni++) {
            o[ni][0] *= clo; o[ni][1] *= clo;
            o[ni][2] *= chi; o[ni][3] *= chi;
        }

        uint32_t pa[4][4];
#pragma unroll
        for (int kc = 0; kc < 4; kc++) {
            pa[kc][0] = h2pack(s[2 * kc][1],     s[2 * kc][0]);
            pa[kc][1] = h2pack(s[2 * kc][3],     s[2 * kc][2]);
            pa[kc][2] = h2pack(s[2 * kc + 1][1], s[2 * kc + 1][0]);
            pa[kc][3] = h2pack(s[2 * kc + 1][3], s[2 * kc + 1][2]);
        }

#pragma unroll
        for (int vc = 0; vc < 2; vc++) {
#pragma unroll
            for (int ni = 0; ni < 16; ni++) {
                uint32_t vb4[4];
                ldsm_x4(vb4[0], vb4[1], vb4[2], vb4[3],
                        vsb + ((ni * 8 + brow) * VLDH + vc * 32 + bcol) * 2);
                mma_h(o[ni], pa[vc * 2],     vb4[0], vb4[1]);
                mma_h(o[ni], pa[vc * 2 + 1], vb4[2], vb4[3]);
            }
        }
    }

    // deferred quad-reduction of l (identical corr applied to all partials)
    l_lo += __shfl_xor_sync(0xffffffffu, l_lo, 1);
    l_lo += __shfl_xor_sync(0xffffffffu, l_lo, 2);
    l_hi += __shfl_xor_sync(0xffffffffu, l_hi, 1);
    l_hi += __shfl_xor_sync(0xffffffffu, l_hi, 2);

    const float il0 = 1.f / l_lo, il1 = 1.f / l_hi;
    __half* olo = Og + (size_t)(b * S_LEN + row_lo) * HIDDEN + h * HD;
    __half* ohi = Og + (size_t)(b * S_LEN + row_hi) * HIDDEN + h * HD;
#pragma unroll
    for (int ni = 0; ni < 16; ni++) {
        int col = ni * 8 + 2 * t4;
        *(__half2*)(olo + col) = __floats2half2_rn(o[ni][0] * il0, o[ni][1] * il0);
        *(__half2*)(ohi + col) = __floats2half2_rn(o[ni][2] * il1, o[ni][3] * il1);
    }
}

// ---------------- launch ----------------
extern "C" void kernel_launch(void* const* d_in, const int* in_sizes, int n_in,
                              void* d_out, int out_size)
{
    const float* h       = (const float*)d_in[0];
    const float* Wq      = (const float*)d_in[3];
    const float* Wkv     = (const float*)d_in[4];
    const float* Wk_up   = (const float*)d_in[5];
    const float* Wv_up   = (const float*)d_in[6];
    const float* Wq_rope = (const float*)d_in[7];
    const float* Wk_rope = (const float*)d_in[8];
    const float* Wo      = (const float*)d_in[9];
    float* out = (float*)d_out;

    __half *ph16, *pWT, *pWkT, *pWvT, *pWoT, *pqkv, *pk, *pvt, *pao;
    cudaGetSymbolAddress((void**)&ph16, g_h16);
    cudaGetSymbolAddress((void**)&pWT,  g_WqkvT);
    cudaGetSymbolAddress((void**)&pWkT, g_WkT);
    cudaGetSymbolAddress((void**)&pWvT, g_WvT);
    cudaGetSymbolAddress((void**)&pWoT, g_WoT);
    cudaGetSymbolAddress((void**)&pqkv, g_qkv16);
    cudaGetSymbolAddress((void**)&pk,   g_k16);
    cudaGetSymbolAddress((void**)&pvt,  g_vt16);
    cudaGetSymbolAddress((void**)&pao,  g_ao16);

    static int attr_done = 0;
    if (!attr_done) {
        cudaFuncSetAttribute(gemm_h,
            cudaFuncAttributeMaxDynamicSharedMemorySize, G_SMEM_BYTES);
        cudaFuncSetAttribute(gemm_kv,
            cudaFuncAttributeMaxDynamicSharedMemorySize, G_SMEM_BYTES);
        cudaFuncSetAttribute(flash_attn_h,
            cudaFuncAttributeMaxDynamicSharedMemorySize, FA_SMEM_BYTES);
        attr_done = 1;
    }

    dim3 blk(256);
    // launch 0: prepass (h cvt + all weight transposes)
    prepass_all<<<20480, dim3(32, 8)>>>(h, Wq, Wq_rope, Wkv, Wk_up, Wk_rope,
                                        Wv_up, Wo, ph16, pWT, pWkT, pWvT, pWoT);

    // launch 1: qkv = fp16(h @ [Wq_eff*s | Wkv])
    gemm_h<<<dim3(QKV_N / GBN, ROWS / GBM), blk, G_SMEM_BYTES>>>(
        ROWS, QKV_N, HIDDEN, ph16, HIDDEN, pWT, HIDDEN, pqkv, QKV_N, 1.f, 1);

    // launch 2: k AND v^T in one launch (grid.z)
    gemm_kv<<<dim3(HIDDEN / GBN, ROWS / GBM, 2), blk, G_SMEM_BYTES>>>(
        pqkv, pWkT, pWvT, pk, pvt);

    // launch 3: attention — Br=64, 128 threads, 2 CTAs/SM
    flash_attn_h<<<dim3(S_LEN / 64, BATCH * NHEADS), 128, FA_SMEM_BYTES>>>(
        pqkv, pk, pvt, pao);

    // launch 4: out = fp32(ao @ Wo)
    gemm_h<<<dim3(HIDDEN / GBN, ROWS / GBM), blk, G_SMEM_BYTES>>>(
        ROWS, HIDDEN, HIDDEN, pao, HIDDEN, pWoT, HIDDEN, out, HIDDEN, 1.f, 0);
}